// round 5
// baseline (speedup 1.0000x reference)
#include <cuda_runtime.h>
#include <cuda_bf16.h>
#include <cstdint>

#define BATCH 4
#define SEQ   4096
#define DIM   512

#define NSD (4ull*4096ull*512ull)     // 8,388,608
#define NW  (3ull*512ull*512ull)      // 786,432
#define NSS (4ull*4096ull*4096ull)    // 67,108,864

// ---------------- static scratch (allocation-free) ----------------
__device__ __nv_bfloat16 g_Xh[NSD], g_Xl[NSD];
__device__ __nv_bfloat16 g_Wh[NW],  g_Wl[NW];
__device__ __nv_bfloat16 g_Qh[NSD], g_Ql[NSD];
__device__ __nv_bfloat16 g_Kh[NSD], g_Kl[NSD];
__device__ __nv_bfloat16 g_Vh[NSD], g_Vl[NSD];
__device__ __nv_bfloat16 g_VTh[NSD], g_VTl[NSD];
__device__ float         g_P[NSS];
__device__ __nv_bfloat16 g_Ph[NSS], g_Pl[NSS];

// ---------------- PTX helpers (compute_103-baseline ISA only) ----------------
__device__ __forceinline__ uint32_t smem_u32(const void* p) {
    uint32_t a;
    asm("{ .reg .u64 t; cvta.to.shared.u64 t, %1; cvt.u32.u64 %0, t; }" : "=r"(a) : "l"(p));
    return a;
}

__device__ __forceinline__ void cp16(uint32_t s, const void* g) {
    asm volatile("cp.async.cg.shared.global [%0], [%1], 16;" :: "r"(s), "l"(g) : "memory");
}
#define CP_COMMIT() asm volatile("cp.async.commit_group;" ::: "memory")
#define CP_WAIT(n)  asm volatile("cp.async.wait_group %0;" :: "n"(n) : "memory")

__device__ __forceinline__ void ldm4(uint32_t addr, uint32_t r[4]) {
    asm volatile("ldmatrix.sync.aligned.m8n8.x4.shared.b16 {%0,%1,%2,%3}, [%4];"
                 : "=r"(r[0]), "=r"(r[1]), "=r"(r[2]), "=r"(r[3]) : "r"(addr));
}

__device__ __forceinline__ void mma16816(float* c, const uint32_t* a, uint32_t b0, uint32_t b1) {
    asm volatile(
        "mma.sync.aligned.m16n8k16.row.col.f32.bf16.bf16.f32 "
        "{%0,%1,%2,%3}, {%4,%5,%6,%7}, {%8,%9}, {%0,%1,%2,%3};"
        : "+f"(c[0]), "+f"(c[1]), "+f"(c[2]), "+f"(c[3])
        : "r"(a[0]), "r"(a[1]), "r"(a[2]), "r"(a[3]), "r"(b0), "r"(b1));
}

// ---------------- GEMM config ----------------
// CTA tile 128x128, 128 thr = 4 warps (2 M x 2 N), warp tile 64x64.
// K-chunk 32 bf16. SMEM rows padded to 80B -> conflict-free ldmatrix.
// 2 CTAs/SM co-resident (2 x 80KB smem, 128 thr x <=255 regs).
#define ROWP     80
#define TILE_B   (128 * ROWP)          // 10240
#define OFF_AH   0
#define OFF_AL   (1 * TILE_B)
#define OFF_BH   (2 * TILE_B)
#define OFF_BL   (3 * TILE_B)
#define STAGE_B  (4 * TILE_B)          // 40960
#define SMEM_ALLOC (2 * STAGE_B)       // 81920
#define NTHR     128

// one 128x32-bf16 tile -> smem (16B chunks, 4 per row); 128 threads
__device__ __forceinline__ void fill_tile(uint32_t sb, const __nv_bfloat16* __restrict__ src,
                                          int ld, int k0, int tid) {
#pragma unroll
    for (int v = 0; v < 4; ++v) {
        int idx = v * NTHR + tid;         // 0..511
        int row = idx >> 2;               // 0..127
        int c16 = idx & 3;                // 0..3
        cp16(sb + row * ROWP + c16 * 16, src + (size_t)row * ld + k0 + c16 * 8);
    }
}

__device__ __forceinline__ void fill_chunk(uint32_t sb,
    const __nv_bfloat16* Ah, const __nv_bfloat16* Al, int lda,
    const __nv_bfloat16* Bh, const __nv_bfloat16* Bl, int ldb,
    int k0, int tid)
{
    fill_tile(sb + OFF_AH, Ah, lda, k0, tid);
    fill_tile(sb + OFF_AL, Al, lda, k0, tid);
    fill_tile(sb + OFF_BH, Bh, ldb, k0, tid);
    fill_tile(sb + OFF_BL, Bl, ldb, k0, tid);
}

// bf16x3 mainloop: acc(128x128 fp32) = (Ah+Al)(Bh+Bl)^T, dropping Al*Bl.
// acc[mf][nf][4]: warp 64x64 tile, mf = m16 frag (4), nf = n8 frag (8).
__device__ __forceinline__ void gemm_bf16x3(
    const __nv_bfloat16* __restrict__ Ah, const __nv_bfloat16* __restrict__ Al, int lda,
    const __nv_bfloat16* __restrict__ Bh, const __nv_bfloat16* __restrict__ Bl, int ldb,
    int ktotal, float acc[4][8][4])
{
    extern __shared__ char rawsm[];
    const uint32_t smb = smem_u32(rawsm);
    const int tid  = threadIdx.x;
    const int lane = tid & 31;
    const int wid  = tid >> 5;
    const int wm   = wid >> 1;   // 0..1
    const int wn   = wid & 1;    // 0..1

#pragma unroll
    for (int i = 0; i < 4; ++i)
#pragma unroll
        for (int j = 0; j < 8; ++j)
#pragma unroll
            for (int k = 0; k < 4; ++k) acc[i][j][k] = 0.f;

    const int nch = ktotal >> 5;

    fill_chunk(smb, Ah, Al, lda, Bh, Bl, ldb, 0, tid);
    CP_COMMIT();

    const uint32_t a_row_off = (uint32_t)((wm * 64 + (lane & 15)) * ROWP);
    const uint32_t b_row_off = (uint32_t)((wn * 64 + (lane & 7) + ((lane >> 3) & 1) * 8) * ROWP);
    const uint32_t k_half    = (uint32_t)(((lane >> 4) & 1) * 16);

    for (int c = 0; c < nch; ++c) {
        if (c + 1 < nch) {
            fill_chunk(smb + (uint32_t)(((c + 1) & 1) * STAGE_B),
                       Ah, Al, lda, Bh, Bl, ldb, (c + 1) << 5, tid);
            CP_COMMIT();
            CP_WAIT(1);
        } else {
            CP_WAIT(0);
        }
        __syncthreads();

        const uint32_t sb = smb + (uint32_t)((c & 1) * STAGE_B);

#pragma unroll
        for (int ks = 0; ks < 2; ++ks) {
            const uint32_t ko = (uint32_t)(ks * 32) + k_half;

            uint32_t ra_h[4][4], ra_l[4][4], rb_h[4][4], rb_l[4][4];
#pragma unroll
            for (int mf = 0; mf < 4; ++mf) {
                ldm4(sb + OFF_AH + a_row_off + (uint32_t)(mf * 16 * ROWP) + ko, ra_h[mf]);
                ldm4(sb + OFF_AL + a_row_off + (uint32_t)(mf * 16 * ROWP) + ko, ra_l[mf]);
            }
#pragma unroll
            for (int bf = 0; bf < 4; ++bf) {
                ldm4(sb + OFF_BH + b_row_off + (uint32_t)(bf * 16 * ROWP) + ko, rb_h[bf]);
                ldm4(sb + OFF_BL + b_row_off + (uint32_t)(bf * 16 * ROWP) + ko, rb_l[bf]);
            }
            // pass 1: Ah*Bh  (each acc frag touched once per pass -> long RAW distance)
#pragma unroll
            for (int mf = 0; mf < 4; ++mf)
#pragma unroll
                for (int bf = 0; bf < 4; ++bf) {
                    mma16816(acc[mf][bf * 2],     ra_h[mf], rb_h[bf][0], rb_h[bf][2]);
                    mma16816(acc[mf][bf * 2 + 1], ra_h[mf], rb_h[bf][1], rb_h[bf][3]);
                }
            // pass 2: Ah*Bl
#pragma unroll
            for (int mf = 0; mf < 4; ++mf)
#pragma unroll
                for (int bf = 0; bf < 4; ++bf) {
                    mma16816(acc[mf][bf * 2],     ra_h[mf], rb_l[bf][0], rb_l[bf][2]);
                    mma16816(acc[mf][bf * 2 + 1], ra_h[mf], rb_l[bf][1], rb_l[bf][3]);
                }
            // pass 3: Al*Bh
#pragma unroll
            for (int mf = 0; mf < 4; ++mf)
#pragma unroll
                for (int bf = 0; bf < 4; ++bf) {
                    mma16816(acc[mf][bf * 2],     ra_l[mf], rb_h[bf][0], rb_h[bf][2]);
                    mma16816(acc[mf][bf * 2 + 1], ra_l[mf], rb_h[bf][1], rb_h[bf][3]);
                }
        }
        __syncthreads();
    }
}

// ---------------- stage kernels ----------------

__global__ __launch_bounds__(1024) void convert_x_kernel(const float* __restrict__ x) {
    size_t i = (size_t)blockIdx.x * blockDim.x + threadIdx.x;
    if (i >= NSD) return;
    float v = x[i];
    __nv_bfloat16 h = __float2bfloat16(v);
    g_Xh[i] = h;
    g_Xl[i] = __float2bfloat16(v - __bfloat162float(h));
}

__global__ __launch_bounds__(1024) void convert_w_kernel(const float* __restrict__ wq,
                                                         const float* __restrict__ wk,
                                                         const float* __restrict__ wv) {
    size_t i = (size_t)blockIdx.x * blockDim.x + threadIdx.x;
    if (i >= NW) return;
    size_t which = i >> 18;
    size_t off   = i & 262143ull;
    const float* src = (which == 0) ? wq : (which == 1) ? wk : wv;
    float v = src[off];
    __nv_bfloat16 h = __float2bfloat16(v);
    g_Wh[i] = h;
    g_Wl[i] = __float2bfloat16(v - __bfloat162float(h));
}

// QKV projection: grid (4 ntile, 128 mtile, 3 which)
__global__ __launch_bounds__(NTHR) void proj_kernel() {
    const int nt = blockIdx.x, mt = blockIdx.y, z = blockIdx.z;
    const __nv_bfloat16* Ah = g_Xh + (size_t)mt * 128 * DIM;
    const __nv_bfloat16* Al = g_Xl + (size_t)mt * 128 * DIM;
    const __nv_bfloat16* Bh = g_Wh + (size_t)z * DIM * DIM + (size_t)nt * 128 * DIM;
    const __nv_bfloat16* Bl = g_Wl + (size_t)z * DIM * DIM + (size_t)nt * 128 * DIM;

    float acc[4][8][4];
    gemm_bf16x3(Ah, Al, DIM, Bh, Bl, DIM, DIM, acc);

    __nv_bfloat16* Ch = (z == 0) ? g_Qh : (z == 1) ? g_Kh : g_Vh;
    __nv_bfloat16* Cl = (z == 0) ? g_Ql : (z == 1) ? g_Kl : g_Vl;

    const int lane = threadIdx.x & 31, wid = threadIdx.x >> 5;
    const int wm = wid >> 1, wn = wid & 1;
    const int g = lane >> 2, t = lane & 3;
    const size_t rbase = (size_t)mt * 128;
    const int cbase = nt * 128 + wn * 64 + 2 * t;

#pragma unroll
    for (int mf = 0; mf < 4; ++mf) {
#pragma unroll
        for (int nf = 0; nf < 8; ++nf) {
            const int col = cbase + nf * 8;
#pragma unroll
            for (int half = 0; half < 2; ++half) {
                const int row = wm * 64 + mf * 16 + g + half * 8;
                float v0 = acc[mf][nf][half * 2];
                float v1 = acc[mf][nf][half * 2 + 1];
                __nv_bfloat16 h0 = __float2bfloat16(v0);
                __nv_bfloat16 h1 = __float2bfloat16(v1);
                __nv_bfloat16 l0 = __float2bfloat16(v0 - __bfloat162float(h0));
                __nv_bfloat16 l1 = __float2bfloat16(v1 - __bfloat162float(h1));
                size_t o = (rbase + row) * DIM + col;
                *reinterpret_cast<__nv_bfloat162*>(Ch + o) = __nv_bfloat162(h0, h1);
                *reinterpret_cast<__nv_bfloat162*>(Cl + o) = __nv_bfloat162(l0, l1);
            }
        }
    }
}

// Transpose V (per batch) -> VT [D, S]
__global__ __launch_bounds__(256) void transpose_v_kernel() {
    __shared__ __nv_bfloat16 th[32][33], tl[32][33];
    const int b = blockIdx.z;
    const int d0 = blockIdx.x * 32, s0 = blockIdx.y * 32;
    const int tx = threadIdx.x, ty = threadIdx.y;
#pragma unroll
    for (int rr = ty; rr < 32; rr += 8) {
        size_t src = ((size_t)b * SEQ + s0 + rr) * DIM + d0 + tx;
        th[rr][tx] = g_Vh[src];
        tl[rr][tx] = g_Vl[src];
    }
    __syncthreads();
#pragma unroll
    for (int rr = ty; rr < 32; rr += 8) {
        size_t dst = ((size_t)b * DIM + d0 + rr) * SEQ + s0 + tx;
        g_VTh[dst] = th[tx][rr];
        g_VTl[dst] = tl[tx][rr];
    }
}

// Scores: grid (32 kt, 32 qt, 4 b), skip kt > qt
__global__ __launch_bounds__(NTHR) void scores_kernel() {
    const int kt = blockIdx.x, qt = blockIdx.y, b = blockIdx.z;
    if (kt > qt) return;

    const size_t qoff = ((size_t)b * SEQ + (size_t)qt * 128) * DIM;
    const size_t koff = ((size_t)b * SEQ + (size_t)kt * 128) * DIM;

    float acc[4][8][4];
    gemm_bf16x3(g_Qh + qoff, g_Ql + qoff, DIM,
                g_Kh + koff, g_Kl + koff, DIM, DIM, acc);

    const int lane = threadIdx.x & 31, wid = threadIdx.x >> 5;
    const int wm = wid >> 1, wn = wid & 1;
    const int g = lane >> 2, t = lane & 3;
    const float scale = 0.04419417382415922f;   // 1/sqrt(512)

#pragma unroll
    for (int mf = 0; mf < 4; ++mf) {
#pragma unroll
        for (int nf = 0; nf < 8; ++nf) {
            const int col = kt * 128 + wn * 64 + nf * 8 + 2 * t;
#pragma unroll
            for (int half = 0; half < 2; ++half) {
                const int qrow = qt * 128 + wm * 64 + mf * 16 + g + half * 8;
                float v0 = (col     <= qrow) ? acc[mf][nf][half * 2]     * scale : -1e30f;
                float v1 = (col + 1 <= qrow) ? acc[mf][nf][half * 2 + 1] * scale : -1e30f;
                float* dst = g_P + ((size_t)b * SEQ + qrow) * SEQ + col;
                *reinterpret_cast<float2*>(dst) = make_float2(v0, v1);
            }
        }
    }
}

// Row softmax over [0, jend): one gmem read, row cached in registers.
__global__ __launch_bounds__(256) void softmax_kernel() {
    const int rr = blockIdx.x;
    const int b = rr >> 12;
    const int i = rr & 4095;
    const size_t rowoff = ((size_t)b * SEQ + i) * SEQ;
    const float* row = g_P + rowoff;
    const int jend = ((i >> 7) + 1) << 7;

    const int tid = threadIdx.x, lane = tid & 31, wid = tid >> 5;
    __shared__ float red[8];

    float v[16];
    int cnt = 0;
    float m = -1e30f;
    for (int j = tid; j < jend; j += 256) {
        float x = row[j];
        v[cnt++] = x;
        m = fmaxf(m, x);
    }
#pragma unroll
    for (int o = 16; o > 0; o >>= 1) m = fmaxf(m, __shfl_xor_sync(0xffffffffu, m, o));
    if (lane == 0) red[wid] = m;
    __syncthreads();
    m = red[0];
#pragma unroll
    for (int w = 1; w < 8; w++) m = fmaxf(m, red[w]);

    float s = 0.f;
    for (int k = 0; k < cnt; ++k) {
        float e = __expf(v[k] - m);
        v[k] = e;
        s += e;
    }
#pragma unroll
    for (int o = 16; o > 0; o >>= 1) s += __shfl_xor_sync(0xffffffffu, s, o);
    __syncthreads();
    if (lane == 0) red[wid] = s;
    __syncthreads();
    s = red[0];
#pragma unroll
    for (int w = 1; w < 8; w++) s += red[w];

    const float inv = 1.0f / s;
    cnt = 0;
    for (int j = tid; j < jend; j += 256) {
        float e = v[cnt++] * inv;
        __nv_bfloat16 h = __float2bfloat16(e);
        g_Ph[rowoff + j] = h;
        g_Pl[rowoff + j] = __float2bfloat16(e - __bfloat162float(h));
    }
}

// PV: grid (4 ntile, 32 qt, 4 b), K bounded by causal extent
__global__ __launch_bounds__(NTHR) void pv_kernel(float* __restrict__ out) {
    const int nt = blockIdx.x, qt = blockIdx.y, b = blockIdx.z;

    const size_t poff = ((size_t)b * SEQ + (size_t)qt * 128) * SEQ;
    const size_t voff = ((size_t)b * DIM + (size_t)nt * 128) * SEQ;
    const int kmax = (qt + 1) * 128;

    float acc[4][8][4];
    gemm_bf16x3(g_Ph + poff, g_Pl + poff, SEQ,
                g_VTh + voff, g_VTl + voff, SEQ, kmax, acc);

    const int lane = threadIdx.x & 31, wid = threadIdx.x >> 5;
    const int wm = wid >> 1, wn = wid & 1;
    const int g = lane >> 2, t = lane & 3;

#pragma unroll
    for (int mf = 0; mf < 4; ++mf) {
#pragma unroll
        for (int nf = 0; nf < 8; ++nf) {
            const int col = nt * 128 + wn * 64 + nf * 8 + 2 * t;
#pragma unroll
            for (int half = 0; half < 2; ++half) {
                const int row = qt * 128 + wm * 64 + mf * 16 + g + half * 8;
                float* dst = out + ((size_t)b * SEQ + row) * DIM + col;
                *reinterpret_cast<float2*>(dst) =
                    make_float2(acc[mf][nf][half * 2], acc[mf][nf][half * 2 + 1]);
            }
        }
    }
}

// ---------------- launch ----------------
extern "C" void kernel_launch(void* const* d_in, const int* in_sizes, int n_in,
                              void* d_out, int out_size)
{
    const float* x  = (const float*)d_in[0];
    const float* WQ = (const float*)d_in[1];
    const float* WK = (const float*)d_in[2];
    const float* WV = (const float*)d_in[3];
    float* out = (float*)d_out;

    cudaFuncSetAttribute(proj_kernel,   cudaFuncAttributeMaxDynamicSharedMemorySize, SMEM_ALLOC);
    cudaFuncSetAttribute(scores_kernel, cudaFuncAttributeMaxDynamicSharedMemorySize, SMEM_ALLOC);
    cudaFuncSetAttribute(pv_kernel,     cudaFuncAttributeMaxDynamicSharedMemorySize, SMEM_ALLOC);

    convert_x_kernel<<<8192, 1024>>>(x);
    convert_w_kernel<<<768, 1024>>>(WQ, WK, WV);

    proj_kernel<<<dim3(4, 128, 3), NTHR, SMEM_ALLOC>>>();

    transpose_v_kernel<<<dim3(16, 128, 4), dim3(32, 8)>>>();

    scores_kernel<<<dim3(32, 32, 4), NTHR, SMEM_ALLOC>>>();

    softmax_kernel<<<BATCH * SEQ, 256>>>();

    pv_kernel<<<dim3(4, 32, 4), NTHR, SMEM_ALLOC>>>(out);
}

// round 6
// speedup vs baseline: 1.6153x; 1.6153x over previous
#include <cuda_runtime.h>
#include <cuda_bf16.h>
#include <cstdint>

#define BATCH 4
#define SEQ   4096
#define DIM   512

#define NSD (4ull*4096ull*512ull)     // 8,388,608
#define NW  (3ull*512ull*512ull)      // 786,432
#define NSS (4ull*4096ull*4096ull)    // 67,108,864

// ---------------- static scratch (allocation-free) ----------------
__device__ __nv_bfloat16 g_Xh[NSD], g_Xl[NSD];
__device__ __nv_bfloat16 g_Wh[NW],  g_Wl[NW];
__device__ __nv_bfloat16 g_Qh[NSD], g_Ql[NSD];
__device__ __nv_bfloat16 g_Kh[NSD], g_Kl[NSD];
__device__ __nv_bfloat16 g_Vh[NSD], g_Vl[NSD];
__device__ __nv_bfloat16 g_VTh[NSD], g_VTl[NSD];
__device__ float         g_P[NSS];
__device__ __nv_bfloat16 g_Ph[NSS], g_Pl[NSS];

// ---------------- PTX helpers (compute_103-baseline ISA only) ----------------
__device__ __forceinline__ uint32_t smem_u32(const void* p) {
    uint32_t a;
    asm("{ .reg .u64 t; cvta.to.shared.u64 t, %1; cvt.u32.u64 %0, t; }" : "=r"(a) : "l"(p));
    return a;
}

__device__ __forceinline__ void cp16(uint32_t s, const void* g) {
    asm volatile("cp.async.cg.shared.global [%0], [%1], 16;" :: "r"(s), "l"(g) : "memory");
}
#define CP_COMMIT() asm volatile("cp.async.commit_group;" ::: "memory")
#define CP_WAIT(n)  asm volatile("cp.async.wait_group %0;" :: "n"(n) : "memory")

__device__ __forceinline__ void ldm4(uint32_t addr, uint32_t r[4]) {
    asm volatile("ldmatrix.sync.aligned.m8n8.x4.shared.b16 {%0,%1,%2,%3}, [%4];"
                 : "=r"(r[0]), "=r"(r[1]), "=r"(r[2]), "=r"(r[3]) : "r"(addr));
}

__device__ __forceinline__ void mma16816(float* c, const uint32_t* a, uint32_t b0, uint32_t b1) {
    asm volatile(
        "mma.sync.aligned.m16n8k16.row.col.f32.bf16.bf16.f32 "
        "{%0,%1,%2,%3}, {%4,%5,%6,%7}, {%8,%9}, {%0,%1,%2,%3};"
        : "+f"(c[0]), "+f"(c[1]), "+f"(c[2]), "+f"(c[3])
        : "r"(a[0]), "r"(a[1]), "r"(a[2]), "r"(a[3]), "r"(b0), "r"(b1));
}

// ---------------- GEMM config ----------------
// CTA tile 128x128, 256 thr = 8 warps (2 M x 4 N), warp tile 64x32.
// K-chunk 64 bf16 (128B data + 16B pad per row -> conflict-free ldmatrix).
// Double-buffered, ONE sync + ONE wait per chunk.
#define ROWP     144
#define TILE_B   (128 * ROWP)          // 18432
#define OFF_AH   0
#define OFF_AL   (1 * TILE_B)
#define OFF_BH   (2 * TILE_B)
#define OFF_BL   (3 * TILE_B)
#define STAGE_B  (4 * TILE_B)          // 73728
#define SMEM_ALLOC (2 * STAGE_B)       // 147456
#define NTHR     256

// one 128x64-bf16 tile -> smem (16B chunks, 8 per row); 256 threads
__device__ __forceinline__ void fill_tile(uint32_t sb, const __nv_bfloat16* __restrict__ src,
                                          int ld, int k0, int tid) {
#pragma unroll
    for (int v = 0; v < 4; ++v) {
        int idx = v * NTHR + tid;         // 0..1023
        int row = idx >> 3;               // 0..127
        int c16 = idx & 7;                // 0..7
        cp16(sb + row * ROWP + c16 * 16, src + (size_t)row * ld + k0 + c16 * 8);
    }
}

__device__ __forceinline__ void fill_chunk(uint32_t sb,
    const __nv_bfloat16* Ah, const __nv_bfloat16* Al, int lda,
    const __nv_bfloat16* Bh, const __nv_bfloat16* Bl, int ldb,
    int k0, int tid)
{
    fill_tile(sb + OFF_AH, Ah, lda, k0, tid);
    fill_tile(sb + OFF_AL, Al, lda, k0, tid);
    fill_tile(sb + OFF_BH, Bh, ldb, k0, tid);
    fill_tile(sb + OFF_BL, Bl, ldb, k0, tid);
}

// bf16x3 mainloop: acc(128x128 fp32) = (Ah+Al)(Bh+Bl)^T, dropping Al*Bl.
// acc[mf][nf][4] per thread (warp 64x32 tile, m16n8 fragments).
__device__ __forceinline__ void gemm_bf16x3(
    const __nv_bfloat16* __restrict__ Ah, const __nv_bfloat16* __restrict__ Al, int lda,
    const __nv_bfloat16* __restrict__ Bh, const __nv_bfloat16* __restrict__ Bl, int ldb,
    int ktotal, float acc[4][4][4])
{
    extern __shared__ char rawsm[];
    const uint32_t smb = smem_u32(rawsm);
    const int tid  = threadIdx.x;
    const int lane = tid & 31;
    const int wid  = tid >> 5;
    const int wm   = wid >> 2;   // 0..1
    const int wn   = wid & 3;    // 0..3

#pragma unroll
    for (int i = 0; i < 4; ++i)
#pragma unroll
        for (int j = 0; j < 4; ++j)
#pragma unroll
            for (int k = 0; k < 4; ++k) acc[i][j][k] = 0.f;

    const int nch = ktotal >> 6;

    fill_chunk(smb, Ah, Al, lda, Bh, Bl, ldb, 0, tid);
    CP_COMMIT();

    const uint32_t a_row_off = (uint32_t)((wm * 64 + (lane & 15)) * ROWP);
    const uint32_t b_row_off = (uint32_t)((wn * 32 + (lane & 7) + ((lane >> 3) & 1) * 8) * ROWP);
    const uint32_t k_half    = (uint32_t)(((lane >> 4) & 1) * 16);

    for (int c = 0; c < nch; ++c) {
        // chunk c's loads (committed last iteration / prologue) must land
        CP_WAIT(0);
        __syncthreads();
        // issue chunk c+1 into the other buffer; its previous readers (chunk
        // c-1) finished before the sync above, so this is safe and overlaps
        // the whole MMA phase below.
        if (c + 1 < nch) {
            fill_chunk(smb + (uint32_t)(((c + 1) & 1) * STAGE_B),
                       Ah, Al, lda, Bh, Bl, ldb, (c + 1) << 6, tid);
            CP_COMMIT();
        }

        const uint32_t sb = smb + (uint32_t)((c & 1) * STAGE_B);

#pragma unroll
        for (int ks = 0; ks < 4; ++ks) {
            const uint32_t ko = (uint32_t)(ks * 32) + k_half;

            uint32_t ra_h[4][4], ra_l[4][4], rb_h[2][4], rb_l[2][4];
#pragma unroll
            for (int mf = 0; mf < 4; ++mf) {
                ldm4(sb + OFF_AH + a_row_off + (uint32_t)(mf * 16 * ROWP) + ko, ra_h[mf]);
                ldm4(sb + OFF_AL + a_row_off + (uint32_t)(mf * 16 * ROWP) + ko, ra_l[mf]);
            }
#pragma unroll
            for (int bf = 0; bf < 2; ++bf) {
                ldm4(sb + OFF_BH + b_row_off + (uint32_t)(bf * 16 * ROWP) + ko, rb_h[bf]);
                ldm4(sb + OFF_BL + b_row_off + (uint32_t)(bf * 16 * ROWP) + ko, rb_l[bf]);
            }
            // pass 1: Ah*Bh  (acc frags touched once per pass -> RAW distance 16)
#pragma unroll
            for (int mf = 0; mf < 4; ++mf)
#pragma unroll
                for (int bf = 0; bf < 2; ++bf) {
                    mma16816(acc[mf][bf * 2],     ra_h[mf], rb_h[bf][0], rb_h[bf][2]);
                    mma16816(acc[mf][bf * 2 + 1], ra_h[mf], rb_h[bf][1], rb_h[bf][3]);
                }
            // pass 2: Ah*Bl
#pragma unroll
            for (int mf = 0; mf < 4; ++mf)
#pragma unroll
                for (int bf = 0; bf < 2; ++bf) {
                    mma16816(acc[mf][bf * 2],     ra_h[mf], rb_l[bf][0], rb_l[bf][2]);
                    mma16816(acc[mf][bf * 2 + 1], ra_h[mf], rb_l[bf][1], rb_l[bf][3]);
                }
            // pass 3: Al*Bh
#pragma unroll
            for (int mf = 0; mf < 4; ++mf)
#pragma unroll
                for (int bf = 0; bf < 2; ++bf) {
                    mma16816(acc[mf][bf * 2],     ra_l[mf], rb_h[bf][0], rb_h[bf][2]);
                    mma16816(acc[mf][bf * 2 + 1], ra_l[mf], rb_h[bf][1], rb_h[bf][3]);
                }
        }
    }
    __syncthreads();
}

// ---------------- stage kernels ----------------

__global__ __launch_bounds__(1024) void convert_x_kernel(const float* __restrict__ x) {
    size_t i = (size_t)blockIdx.x * blockDim.x + threadIdx.x;
    if (i >= NSD) return;
    float v = x[i];
    __nv_bfloat16 h = __float2bfloat16(v);
    g_Xh[i] = h;
    g_Xl[i] = __float2bfloat16(v - __bfloat162float(h));
}

__global__ __launch_bounds__(1024) void convert_w_kernel(const float* __restrict__ wq,
                                                         const float* __restrict__ wk,
                                                         const float* __restrict__ wv) {
    size_t i = (size_t)blockIdx.x * blockDim.x + threadIdx.x;
    if (i >= NW) return;
    size_t which = i >> 18;
    size_t off   = i & 262143ull;
    const float* src = (which == 0) ? wq : (which == 1) ? wk : wv;
    float v = src[off];
    __nv_bfloat16 h = __float2bfloat16(v);
    g_Wh[i] = h;
    g_Wl[i] = __float2bfloat16(v - __bfloat162float(h));
}

// QKV projection: grid (4 ntile, 128 mtile, 3 which)
__global__ __launch_bounds__(NTHR) void proj_kernel() {
    const int nt = blockIdx.x, mt = blockIdx.y, z = blockIdx.z;
    const __nv_bfloat16* Ah = g_Xh + (size_t)mt * 128 * DIM;
    const __nv_bfloat16* Al = g_Xl + (size_t)mt * 128 * DIM;
    const __nv_bfloat16* Bh = g_Wh + (size_t)z * DIM * DIM + (size_t)nt * 128 * DIM;
    const __nv_bfloat16* Bl = g_Wl + (size_t)z * DIM * DIM + (size_t)nt * 128 * DIM;

    float acc[4][4][4];
    gemm_bf16x3(Ah, Al, DIM, Bh, Bl, DIM, DIM, acc);

    __nv_bfloat16* Ch = (z == 0) ? g_Qh : (z == 1) ? g_Kh : g_Vh;
    __nv_bfloat16* Cl = (z == 0) ? g_Ql : (z == 1) ? g_Kl : g_Vl;

    const int lane = threadIdx.x & 31, wid = threadIdx.x >> 5;
    const int wm = wid >> 2, wn = wid & 3;
    const int g = lane >> 2, t = lane & 3;
    const size_t rbase = (size_t)mt * 128;
    const int cbase = nt * 128 + wn * 32 + 2 * t;

#pragma unroll
    for (int mf = 0; mf < 4; ++mf) {
#pragma unroll
        for (int nf = 0; nf < 4; ++nf) {
            const int col = cbase + nf * 8;
#pragma unroll
            for (int half = 0; half < 2; ++half) {
                const int row = wm * 64 + mf * 16 + g + half * 8;
                float v0 = acc[mf][nf][half * 2];
                float v1 = acc[mf][nf][half * 2 + 1];
                __nv_bfloat16 h0 = __float2bfloat16(v0);
                __nv_bfloat16 h1 = __float2bfloat16(v1);
                __nv_bfloat16 l0 = __float2bfloat16(v0 - __bfloat162float(h0));
                __nv_bfloat16 l1 = __float2bfloat16(v1 - __bfloat162float(h1));
                size_t o = (rbase + row) * DIM + col;
                *reinterpret_cast<__nv_bfloat162*>(Ch + o) = __nv_bfloat162(h0, h1);
                *reinterpret_cast<__nv_bfloat162*>(Cl + o) = __nv_bfloat162(l0, l1);
            }
        }
    }
}

// Transpose V (per batch) -> VT [D, S]
__global__ __launch_bounds__(256) void transpose_v_kernel() {
    __shared__ __nv_bfloat16 th[32][33], tl[32][33];
    const int b = blockIdx.z;
    const int d0 = blockIdx.x * 32, s0 = blockIdx.y * 32;
    const int tx = threadIdx.x, ty = threadIdx.y;
#pragma unroll
    for (int rr = ty; rr < 32; rr += 8) {
        size_t src = ((size_t)b * SEQ + s0 + rr) * DIM + d0 + tx;
        th[rr][tx] = g_Vh[src];
        tl[rr][tx] = g_Vl[src];
    }
    __syncthreads();
#pragma unroll
    for (int rr = ty; rr < 32; rr += 8) {
        size_t dst = ((size_t)b * DIM + d0 + rr) * SEQ + s0 + tx;
        g_VTh[dst] = th[tx][rr];
        g_VTl[dst] = tl[tx][rr];
    }
}

// Scores: grid (32 kt, 32 qt, 4 b), skip kt > qt
__global__ __launch_bounds__(NTHR) void scores_kernel() {
    const int kt = blockIdx.x, qt = blockIdx.y, b = blockIdx.z;
    if (kt > qt) return;

    const size_t qoff = ((size_t)b * SEQ + (size_t)qt * 128) * DIM;
    const size_t koff = ((size_t)b * SEQ + (size_t)kt * 128) * DIM;

    float acc[4][4][4];
    gemm_bf16x3(g_Qh + qoff, g_Ql + qoff, DIM,
                g_Kh + koff, g_Kl + koff, DIM, DIM, acc);

    const int lane = threadIdx.x & 31, wid = threadIdx.x >> 5;
    const int wm = wid >> 2, wn = wid & 3;
    const int g = lane >> 2, t = lane & 3;
    const float scale = 0.04419417382415922f;   // 1/sqrt(512)

#pragma unroll
    for (int mf = 0; mf < 4; ++mf) {
#pragma unroll
        for (int nf = 0; nf < 4; ++nf) {
            const int col = kt * 128 + wn * 32 + nf * 8 + 2 * t;
#pragma unroll
            for (int half = 0; half < 2; ++half) {
                const int qrow = qt * 128 + wm * 64 + mf * 16 + g + half * 8;
                float v0 = (col     <= qrow) ? acc[mf][nf][half * 2]     * scale : -1e30f;
                float v1 = (col + 1 <= qrow) ? acc[mf][nf][half * 2 + 1] * scale : -1e30f;
                float* dst = g_P + ((size_t)b * SEQ + qrow) * SEQ + col;
                *reinterpret_cast<float2*>(dst) = make_float2(v0, v1);
            }
        }
    }
}

// Row softmax over [0, jend): one gmem read, row cached in registers.
__global__ __launch_bounds__(256) void softmax_kernel() {
    const int rr = blockIdx.x;
    const int b = rr >> 12;
    const int i = rr & 4095;
    const size_t rowoff = ((size_t)b * SEQ + i) * SEQ;
    const float* row = g_P + rowoff;
    const int jend = ((i >> 7) + 1) << 7;

    const int tid = threadIdx.x, lane = tid & 31, wid = tid >> 5;
    __shared__ float red[8];

    float v[16];
    int cnt = 0;
    float m = -1e30f;
    for (int j = tid; j < jend; j += 256) {
        float x = row[j];
        v[cnt++] = x;
        m = fmaxf(m, x);
    }
#pragma unroll
    for (int o = 16; o > 0; o >>= 1) m = fmaxf(m, __shfl_xor_sync(0xffffffffu, m, o));
    if (lane == 0) red[wid] = m;
    __syncthreads();
    m = red[0];
#pragma unroll
    for (int w = 1; w < 8; w++) m = fmaxf(m, red[w]);

    float s = 0.f;
    for (int k = 0; k < cnt; ++k) {
        float e = __expf(v[k] - m);
        v[k] = e;
        s += e;
    }
#pragma unroll
    for (int o = 16; o > 0; o >>= 1) s += __shfl_xor_sync(0xffffffffu, s, o);
    __syncthreads();
    if (lane == 0) red[wid] = s;
    __syncthreads();
    s = red[0];
#pragma unroll
    for (int w = 1; w < 8; w++) s += red[w];

    const float inv = 1.0f / s;
    cnt = 0;
    for (int j = tid; j < jend; j += 256) {
        float e = v[cnt++] * inv;
        __nv_bfloat16 h = __float2bfloat16(e);
        g_Ph[rowoff + j] = h;
        g_Pl[rowoff + j] = __float2bfloat16(e - __bfloat162float(h));
    }
}

// PV: grid (4 ntile, 32 qt, 4 b), K bounded by causal extent
__global__ __launch_bounds__(NTHR) void pv_kernel(float* __restrict__ out) {
    const int nt = blockIdx.x, qt = blockIdx.y, b = blockIdx.z;

    const size_t poff = ((size_t)b * SEQ + (size_t)qt * 128) * SEQ;
    const size_t voff = ((size_t)b * DIM + (size_t)nt * 128) * SEQ;
    const int kmax = (qt + 1) * 128;

    float acc[4][4][4];
    gemm_bf16x3(g_Ph + poff, g_Pl + poff, SEQ,
                g_VTh + voff, g_VTl + voff, SEQ, kmax, acc);

    const int lane = threadIdx.x & 31, wid = threadIdx.x >> 5;
    const int wm = wid >> 2, wn = wid & 3;
    const int g = lane >> 2, t = lane & 3;

#pragma unroll
    for (int mf = 0; mf < 4; ++mf) {
#pragma unroll
        for (int nf = 0; nf < 4; ++nf) {
            const int col = nt * 128 + wn * 32 + nf * 8 + 2 * t;
#pragma unroll
            for (int half = 0; half < 2; ++half) {
                const int row = qt * 128 + wm * 64 + mf * 16 + g + half * 8;
                float* dst = out + ((size_t)b * SEQ + row) * DIM + col;
                *reinterpret_cast<float2*>(dst) =
                    make_float2(acc[mf][nf][half * 2], acc[mf][nf][half * 2 + 1]);
            }
        }
    }
}

// ---------------- launch ----------------
extern "C" void kernel_launch(void* const* d_in, const int* in_sizes, int n_in,
                              void* d_out, int out_size)
{
    const float* x  = (const float*)d_in[0];
    const float* WQ = (const float*)d_in[1];
    const float* WK = (const float*)d_in[2];
    const float* WV = (const float*)d_in[3];
    float* out = (float*)d_out;

    cudaFuncSetAttribute(proj_kernel,   cudaFuncAttributeMaxDynamicSharedMemorySize, SMEM_ALLOC);
    cudaFuncSetAttribute(scores_kernel, cudaFuncAttributeMaxDynamicSharedMemorySize, SMEM_ALLOC);
    cudaFuncSetAttribute(pv_kernel,     cudaFuncAttributeMaxDynamicSharedMemorySize, SMEM_ALLOC);

    convert_x_kernel<<<8192, 1024>>>(x);
    convert_w_kernel<<<768, 1024>>>(WQ, WK, WV);

    proj_kernel<<<dim3(4, 128, 3), NTHR, SMEM_ALLOC>>>();

    transpose_v_kernel<<<dim3(16, 128, 4), dim3(32, 8)>>>();

    scores_kernel<<<dim3(32, 32, 4), NTHR, SMEM_ALLOC>>>();

    softmax_kernel<<<BATCH * SEQ, 256>>>();

    pv_kernel<<<dim3(4, 32, 4), NTHR, SMEM_ALLOC>>>(out);
}

// round 7
// speedup vs baseline: 2.0628x; 1.2770x over previous
#include <cuda_runtime.h>
#include <cuda_bf16.h>
#include <cuda_fp16.h>
#include <cstdint>

#define BATCH 4
#define SEQ   4096
#define DIM   512

#define NSD (4ull*4096ull*512ull)     // 8,388,608
#define NW  (3ull*512ull*512ull)      // 786,432
#define NSS (4ull*4096ull*4096ull)    // 67,108,864

// ---------------- static scratch (allocation-free) ----------------
// proj inputs (bf16x3 path, unchanged)
__device__ __nv_bfloat16 g_Xh[NSD], g_Xl[NSD];
__device__ __nv_bfloat16 g_Wh[NW],  g_Wl[NW];
// fp16 attention operands
__device__ __half g_Qh[NSD], g_Ql[NSD];      // Q split hi/lo
__device__ __half g_Kf[NSD];                 // K plain fp16
__device__ __half g_Vf[NSD];                 // V plain fp16
__device__ __half g_VTf[NSD];                // V^T plain fp16
__device__ float  g_P[NSS];
__device__ __half g_Ph[NSS], g_Pl[NSS];      // probs split hi/lo

// ---------------- PTX helpers (compute_103-baseline ISA only) ----------------
__device__ __forceinline__ uint32_t smem_u32(const void* p) {
    uint32_t a;
    asm("{ .reg .u64 t; cvta.to.shared.u64 t, %1; cvt.u32.u64 %0, t; }" : "=r"(a) : "l"(p));
    return a;
}

__device__ __forceinline__ void cp16(uint32_t s, const void* g) {
    asm volatile("cp.async.cg.shared.global [%0], [%1], 16;" :: "r"(s), "l"(g) : "memory");
}
#define CP_COMMIT() asm volatile("cp.async.commit_group;" ::: "memory")
#define CP_WAIT(n)  asm volatile("cp.async.wait_group %0;" :: "n"(n) : "memory")

__device__ __forceinline__ void ldm4(uint32_t addr, uint32_t r[4]) {
    asm volatile("ldmatrix.sync.aligned.m8n8.x4.shared.b16 {%0,%1,%2,%3}, [%4];"
                 : "=r"(r[0]), "=r"(r[1]), "=r"(r[2]), "=r"(r[3]) : "r"(addr));
}

__device__ __forceinline__ void mma_bf(float* c, const uint32_t* a, uint32_t b0, uint32_t b1) {
    asm volatile(
        "mma.sync.aligned.m16n8k16.row.col.f32.bf16.bf16.f32 "
        "{%0,%1,%2,%3}, {%4,%5,%6,%7}, {%8,%9}, {%0,%1,%2,%3};"
        : "+f"(c[0]), "+f"(c[1]), "+f"(c[2]), "+f"(c[3])
        : "r"(a[0]), "r"(a[1]), "r"(a[2]), "r"(a[3]), "r"(b0), "r"(b1));
}

__device__ __forceinline__ void mma_hf(float* c, const uint32_t* a, uint32_t b0, uint32_t b1) {
    asm volatile(
        "mma.sync.aligned.m16n8k16.row.col.f32.f16.f16.f32 "
        "{%0,%1,%2,%3}, {%4,%5,%6,%7}, {%8,%9}, {%0,%1,%2,%3};"
        : "+f"(c[0]), "+f"(c[1]), "+f"(c[2]), "+f"(c[3])
        : "r"(a[0]), "r"(a[1]), "r"(a[2]), "r"(a[3]), "r"(b0), "r"(b1));
}

// ---------------- GEMM config ----------------
// CTA tile 128x128, 256 thr = 8 warps (2 M x 4 N), warp tile 64x32.
// K-chunk 64 (128B data + 16B pad per row -> conflict-free ldmatrix).
#define ROWP     144
#define TILE_B   (128 * ROWP)          // 18432
// bf16x3 (proj): 4 tiles per stage
#define OFF_AH   0
#define OFF_AL   (1 * TILE_B)
#define OFF_BH   (2 * TILE_B)
#define OFF_BL   (3 * TILE_B)
#define STAGE_B  (4 * TILE_B)          // 73728
#define SMEM_ALLOC (2 * STAGE_B)       // 147456
// fp16x2 (scores/pv): 3 tiles per stage -> 2 CTAs/SM
#define OFF2_AH  0
#define OFF2_AL  (1 * TILE_B)
#define OFF2_B   (2 * TILE_B)
#define STAGE2_B (3 * TILE_B)          // 55296
#define SMEM_ALLOC2 (2 * STAGE2_B)     // 110592
#define NTHR     256

// one 128x64-elem (2B) tile -> smem (16B chunks, 8 per row); 256 threads
template <typename T>
__device__ __forceinline__ void fill_tile(uint32_t sb, const T* __restrict__ src,
                                          int ld, int k0, int tid) {
#pragma unroll
    for (int v = 0; v < 4; ++v) {
        int idx = v * NTHR + tid;         // 0..1023
        int row = idx >> 3;               // 0..127
        int c16 = idx & 7;                // 0..7
        cp16(sb + row * ROWP + c16 * 16, src + (size_t)row * ld + k0 + c16 * 8);
    }
}

// ---------------- bf16x3 mainloop (proj only) ----------------
__device__ __forceinline__ void gemm_bf16x3(
    const __nv_bfloat16* __restrict__ Ah, const __nv_bfloat16* __restrict__ Al, int lda,
    const __nv_bfloat16* __restrict__ Bh, const __nv_bfloat16* __restrict__ Bl, int ldb,
    int ktotal, float acc[4][4][4])
{
    extern __shared__ char rawsm[];
    const uint32_t smb = smem_u32(rawsm);
    const int tid  = threadIdx.x;
    const int lane = tid & 31;
    const int wid  = tid >> 5;
    const int wm   = wid >> 2;
    const int wn   = wid & 3;

#pragma unroll
    for (int i = 0; i < 4; ++i)
#pragma unroll
        for (int j = 0; j < 4; ++j)
#pragma unroll
            for (int k = 0; k < 4; ++k) acc[i][j][k] = 0.f;

    const int nch = ktotal >> 6;

    fill_tile(smb + OFF_AH, Ah, lda, 0, tid);
    fill_tile(smb + OFF_AL, Al, lda, 0, tid);
    fill_tile(smb + OFF_BH, Bh, ldb, 0, tid);
    fill_tile(smb + OFF_BL, Bl, ldb, 0, tid);
    CP_COMMIT();

    const uint32_t a_row_off = (uint32_t)((wm * 64 + (lane & 15)) * ROWP);
    const uint32_t b_row_off = (uint32_t)((wn * 32 + (lane & 7) + ((lane >> 3) & 1) * 8) * ROWP);
    const uint32_t k_half    = (uint32_t)(((lane >> 4) & 1) * 16);

    for (int c = 0; c < nch; ++c) {
        CP_WAIT(0);
        __syncthreads();
        if (c + 1 < nch) {
            const uint32_t nb = smb + (uint32_t)(((c + 1) & 1) * STAGE_B);
            const int nk = (c + 1) << 6;
            fill_tile(nb + OFF_AH, Ah, lda, nk, tid);
            fill_tile(nb + OFF_AL, Al, lda, nk, tid);
            fill_tile(nb + OFF_BH, Bh, ldb, nk, tid);
            fill_tile(nb + OFF_BL, Bl, ldb, nk, tid);
            CP_COMMIT();
        }

        const uint32_t sb = smb + (uint32_t)((c & 1) * STAGE_B);

#pragma unroll
        for (int ks = 0; ks < 4; ++ks) {
            const uint32_t ko = (uint32_t)(ks * 32) + k_half;

            uint32_t ra_h[4][4], ra_l[4][4], rb_h[2][4], rb_l[2][4];
#pragma unroll
            for (int mf = 0; mf < 4; ++mf) {
                ldm4(sb + OFF_AH + a_row_off + (uint32_t)(mf * 16 * ROWP) + ko, ra_h[mf]);
                ldm4(sb + OFF_AL + a_row_off + (uint32_t)(mf * 16 * ROWP) + ko, ra_l[mf]);
            }
#pragma unroll
            for (int bf = 0; bf < 2; ++bf) {
                ldm4(sb + OFF_BH + b_row_off + (uint32_t)(bf * 16 * ROWP) + ko, rb_h[bf]);
                ldm4(sb + OFF_BL + b_row_off + (uint32_t)(bf * 16 * ROWP) + ko, rb_l[bf]);
            }
#pragma unroll
            for (int mf = 0; mf < 4; ++mf)
#pragma unroll
                for (int bf = 0; bf < 2; ++bf) {
                    mma_bf(acc[mf][bf * 2],     ra_h[mf], rb_h[bf][0], rb_h[bf][2]);
                    mma_bf(acc[mf][bf * 2 + 1], ra_h[mf], rb_h[bf][1], rb_h[bf][3]);
                }
#pragma unroll
            for (int mf = 0; mf < 4; ++mf)
#pragma unroll
                for (int bf = 0; bf < 2; ++bf) {
                    mma_bf(acc[mf][bf * 2],     ra_h[mf], rb_l[bf][0], rb_l[bf][2]);
                    mma_bf(acc[mf][bf * 2 + 1], ra_h[mf], rb_l[bf][1], rb_l[bf][3]);
                }
#pragma unroll
            for (int mf = 0; mf < 4; ++mf)
#pragma unroll
                for (int bf = 0; bf < 2; ++bf) {
                    mma_bf(acc[mf][bf * 2],     ra_l[mf], rb_h[bf][0], rb_h[bf][2]);
                    mma_bf(acc[mf][bf * 2 + 1], ra_l[mf], rb_h[bf][1], rb_h[bf][3]);
                }
        }
    }
    __syncthreads();
}

// ---------------- fp16x2 mainloop (scores & pv): A split, B plain ----------------
__device__ __forceinline__ void gemm_fp16x2(
    const __half* __restrict__ Ah, const __half* __restrict__ Al, int lda,
    const __half* __restrict__ B, int ldb,
    int ktotal, float acc[4][4][4])
{
    extern __shared__ char rawsm[];
    const uint32_t smb = smem_u32(rawsm);
    const int tid  = threadIdx.x;
    const int lane = tid & 31;
    const int wid  = tid >> 5;
    const int wm   = wid >> 2;
    const int wn   = wid & 3;

#pragma unroll
    for (int i = 0; i < 4; ++i)
#pragma unroll
        for (int j = 0; j < 4; ++j)
#pragma unroll
            for (int k = 0; k < 4; ++k) acc[i][j][k] = 0.f;

    const int nch = ktotal >> 6;

    fill_tile(smb + OFF2_AH, Ah, lda, 0, tid);
    fill_tile(smb + OFF2_AL, Al, lda, 0, tid);
    fill_tile(smb + OFF2_B,  B,  ldb, 0, tid);
    CP_COMMIT();

    const uint32_t a_row_off = (uint32_t)((wm * 64 + (lane & 15)) * ROWP);
    const uint32_t b_row_off = (uint32_t)((wn * 32 + (lane & 7) + ((lane >> 3) & 1) * 8) * ROWP);
    const uint32_t k_half    = (uint32_t)(((lane >> 4) & 1) * 16);

    for (int c = 0; c < nch; ++c) {
        CP_WAIT(0);
        __syncthreads();
        if (c + 1 < nch) {
            const uint32_t nb = smb + (uint32_t)(((c + 1) & 1) * STAGE2_B);
            const int nk = (c + 1) << 6;
            fill_tile(nb + OFF2_AH, Ah, lda, nk, tid);
            fill_tile(nb + OFF2_AL, Al, lda, nk, tid);
            fill_tile(nb + OFF2_B,  B,  ldb, nk, tid);
            CP_COMMIT();
        }

        const uint32_t sb = smb + (uint32_t)((c & 1) * STAGE2_B);

#pragma unroll
        for (int ks = 0; ks < 4; ++ks) {
            const uint32_t ko = (uint32_t)(ks * 32) + k_half;

            uint32_t ra_h[4][4], ra_l[4][4], rb[2][4];
#pragma unroll
            for (int mf = 0; mf < 4; ++mf) {
                ldm4(sb + OFF2_AH + a_row_off + (uint32_t)(mf * 16 * ROWP) + ko, ra_h[mf]);
                ldm4(sb + OFF2_AL + a_row_off + (uint32_t)(mf * 16 * ROWP) + ko, ra_l[mf]);
            }
#pragma unroll
            for (int bf = 0; bf < 2; ++bf)
                ldm4(sb + OFF2_B + b_row_off + (uint32_t)(bf * 16 * ROWP) + ko, rb[bf]);

            // pass 1: Ah*B
#pragma unroll
            for (int mf = 0; mf < 4; ++mf)
#pragma unroll
                for (int bf = 0; bf < 2; ++bf) {
                    mma_hf(acc[mf][bf * 2],     ra_h[mf], rb[bf][0], rb[bf][2]);
                    mma_hf(acc[mf][bf * 2 + 1], ra_h[mf], rb[bf][1], rb[bf][3]);
                }
            // pass 2: Al*B
#pragma unroll
            for (int mf = 0; mf < 4; ++mf)
#pragma unroll
                for (int bf = 0; bf < 2; ++bf) {
                    mma_hf(acc[mf][bf * 2],     ra_l[mf], rb[bf][0], rb[bf][2]);
                    mma_hf(acc[mf][bf * 2 + 1], ra_l[mf], rb[bf][1], rb[bf][3]);
                }
        }
    }
    __syncthreads();
}

// ---------------- stage kernels ----------------

__global__ __launch_bounds__(1024) void convert_x_kernel(const float* __restrict__ x) {
    size_t i = (size_t)blockIdx.x * blockDim.x + threadIdx.x;
    if (i >= NSD) return;
    float v = x[i];
    __nv_bfloat16 h = __float2bfloat16(v);
    g_Xh[i] = h;
    g_Xl[i] = __float2bfloat16(v - __bfloat162float(h));
}

__global__ __launch_bounds__(1024) void convert_w_kernel(const float* __restrict__ wq,
                                                         const float* __restrict__ wk,
                                                         const float* __restrict__ wv) {
    size_t i = (size_t)blockIdx.x * blockDim.x + threadIdx.x;
    if (i >= NW) return;
    size_t which = i >> 18;
    size_t off   = i & 262143ull;
    const float* src = (which == 0) ? wq : (which == 1) ? wk : wv;
    float v = src[off];
    __nv_bfloat16 h = __float2bfloat16(v);
    g_Wh[i] = h;
    g_Wl[i] = __float2bfloat16(v - __bfloat162float(h));
}

// QKV projection (bf16x3): grid (4 ntile, 128 mtile, 3 which)
// Epilogue: z=0 -> Q fp16 split; z=1 -> K plain fp16; z=2 -> V plain fp16.
__global__ __launch_bounds__(NTHR) void proj_kernel() {
    const int nt = blockIdx.x, mt = blockIdx.y, z = blockIdx.z;
    const __nv_bfloat16* Ah = g_Xh + (size_t)mt * 128 * DIM;
    const __nv_bfloat16* Al = g_Xl + (size_t)mt * 128 * DIM;
    const __nv_bfloat16* Bh = g_Wh + (size_t)z * DIM * DIM + (size_t)nt * 128 * DIM;
    const __nv_bfloat16* Bl = g_Wl + (size_t)z * DIM * DIM + (size_t)nt * 128 * DIM;

    float acc[4][4][4];
    gemm_bf16x3(Ah, Al, DIM, Bh, Bl, DIM, DIM, acc);

    const int lane = threadIdx.x & 31, wid = threadIdx.x >> 5;
    const int wm = wid >> 2, wn = wid & 3;
    const int g = lane >> 2, t = lane & 3;
    const size_t rbase = (size_t)mt * 128;
    const int cbase = nt * 128 + wn * 32 + 2 * t;

#pragma unroll
    for (int mf = 0; mf < 4; ++mf) {
#pragma unroll
        for (int nf = 0; nf < 4; ++nf) {
            const int col = cbase + nf * 8;
#pragma unroll
            for (int half = 0; half < 2; ++half) {
                const int row = wm * 64 + mf * 16 + g + half * 8;
                float v0 = acc[mf][nf][half * 2];
                float v1 = acc[mf][nf][half * 2 + 1];
                size_t o = (rbase + row) * DIM + col;
                if (z == 0) {
                    __half h0 = __float2half_rn(v0);
                    __half h1 = __float2half_rn(v1);
                    __half l0 = __float2half_rn(v0 - __half2float(h0));
                    __half l1 = __float2half_rn(v1 - __half2float(h1));
                    *reinterpret_cast<__half2*>(g_Qh + o) = __halves2half2(h0, h1);
                    *reinterpret_cast<__half2*>(g_Ql + o) = __halves2half2(l0, l1);
                } else {
                    __half* dst = (z == 1) ? g_Kf : g_Vf;
                    *reinterpret_cast<__half2*>(dst + o) =
                        __halves2half2(__float2half_rn(v0), __float2half_rn(v1));
                }
            }
        }
    }
}

// Transpose V (per batch) -> VT [D, S], fp16
__global__ __launch_bounds__(256) void transpose_v_kernel() {
    __shared__ __half th[32][33];
    const int b = blockIdx.z;
    const int d0 = blockIdx.x * 32, s0 = blockIdx.y * 32;
    const int tx = threadIdx.x, ty = threadIdx.y;
#pragma unroll
    for (int rr = ty; rr < 32; rr += 8) {
        size_t src = ((size_t)b * SEQ + s0 + rr) * DIM + d0 + tx;
        th[rr][tx] = g_Vf[src];
    }
    __syncthreads();
#pragma unroll
    for (int rr = ty; rr < 32; rr += 8) {
        size_t dst = ((size_t)b * DIM + d0 + rr) * SEQ + s0 + tx;
        g_VTf[dst] = th[tx][rr];
    }
}

// Scores (fp16x2): grid (32 kt, 32 qt, 4 b), skip kt > qt
__global__ __launch_bounds__(NTHR) void scores_kernel() {
    const int kt = blockIdx.x, qt = blockIdx.y, b = blockIdx.z;
    if (kt > qt) return;

    const size_t qoff = ((size_t)b * SEQ + (size_t)qt * 128) * DIM;
    const size_t koff = ((size_t)b * SEQ + (size_t)kt * 128) * DIM;

    float acc[4][4][4];
    gemm_fp16x2(g_Qh + qoff, g_Ql + qoff, DIM, g_Kf + koff, DIM, DIM, acc);

    const int lane = threadIdx.x & 31, wid = threadIdx.x >> 5;
    const int wm = wid >> 2, wn = wid & 3;
    const int g = lane >> 2, t = lane & 3;
    const float scale = 0.04419417382415922f;   // 1/sqrt(512)

#pragma unroll
    for (int mf = 0; mf < 4; ++mf) {
#pragma unroll
        for (int nf = 0; nf < 4; ++nf) {
            const int col = kt * 128 + wn * 32 + nf * 8 + 2 * t;
#pragma unroll
            for (int half = 0; half < 2; ++half) {
                const int qrow = qt * 128 + wm * 64 + mf * 16 + g + half * 8;
                float v0 = (col     <= qrow) ? acc[mf][nf][half * 2]     * scale : -1e30f;
                float v1 = (col + 1 <= qrow) ? acc[mf][nf][half * 2 + 1] * scale : -1e30f;
                float* dst = g_P + ((size_t)b * SEQ + qrow) * SEQ + col;
                *reinterpret_cast<float2*>(dst) = make_float2(v0, v1);
            }
        }
    }
}

// Row softmax over [0, jend): one gmem read, row cached in registers.
__global__ __launch_bounds__(256) void softmax_kernel() {
    const int rr = blockIdx.x;
    const int b = rr >> 12;
    const int i = rr & 4095;
    const size_t rowoff = ((size_t)b * SEQ + i) * SEQ;
    const float* row = g_P + rowoff;
    const int jend = ((i >> 7) + 1) << 7;

    const int tid = threadIdx.x, lane = tid & 31, wid = tid >> 5;
    __shared__ float red[8];

    float v[16];
    int cnt = 0;
    float m = -1e30f;
    for (int j = tid; j < jend; j += 256) {
        float x = row[j];
        v[cnt++] = x;
        m = fmaxf(m, x);
    }
#pragma unroll
    for (int o = 16; o > 0; o >>= 1) m = fmaxf(m, __shfl_xor_sync(0xffffffffu, m, o));
    if (lane == 0) red[wid] = m;
    __syncthreads();
    m = red[0];
#pragma unroll
    for (int w = 1; w < 8; w++) m = fmaxf(m, red[w]);

    float s = 0.f;
    for (int k = 0; k < cnt; ++k) {
        float e = __expf(v[k] - m);
        v[k] = e;
        s += e;
    }
#pragma unroll
    for (int o = 16; o > 0; o >>= 1) s += __shfl_xor_sync(0xffffffffu, s, o);
    __syncthreads();
    if (lane == 0) red[wid] = s;
    __syncthreads();
    s = red[0];
#pragma unroll
    for (int w = 1; w < 8; w++) s += red[w];

    const float inv = 1.0f / s;
    cnt = 0;
    for (int j = tid; j < jend; j += 256) {
        float e = v[cnt++] * inv;
        __half h = __float2half_rn(e);
        g_Ph[rowoff + j] = h;
        g_Pl[rowoff + j] = __float2half_rn(e - __half2float(h));
    }
}

// PV (fp16x2): grid (4 ntile, 32 qt, 4 b), K bounded by causal extent
__global__ __launch_bounds__(NTHR) void pv_kernel(float* __restrict__ out) {
    const int nt = blockIdx.x, qt = blockIdx.y, b = blockIdx.z;

    const size_t poff = ((size_t)b * SEQ + (size_t)qt * 128) * SEQ;
    const size_t voff = ((size_t)b * DIM + (size_t)nt * 128) * SEQ;
    const int kmax = (qt + 1) * 128;

    float acc[4][4][4];
    gemm_fp16x2(g_Ph + poff, g_Pl + poff, SEQ, g_VTf + voff, SEQ, kmax, acc);

    const int lane = threadIdx.x & 31, wid = threadIdx.x >> 5;
    const int wm = wid >> 2, wn = wid & 3;
    const int g = lane >> 2, t = lane & 3;

#pragma unroll
    for (int mf = 0; mf < 4; ++mf) {
#pragma unroll
        for (int nf = 0; nf < 4; ++nf) {
            const int col = nt * 128 + wn * 32 + nf * 8 + 2 * t;
#pragma unroll
            for (int half = 0; half < 2; ++half) {
                const int row = qt * 128 + wm * 64 + mf * 16 + g + half * 8;
                float* dst = out + ((size_t)b * SEQ + row) * DIM + col;
                *reinterpret_cast<float2*>(dst) =
                    make_float2(acc[mf][nf][half * 2], acc[mf][nf][half * 2 + 1]);
            }
        }
    }
}

// ---------------- launch ----------------
extern "C" void kernel_launch(void* const* d_in, const int* in_sizes, int n_in,
                              void* d_out, int out_size)
{
    const float* x  = (const float*)d_in[0];
    const float* WQ = (const float*)d_in[1];
    const float* WK = (const float*)d_in[2];
    const float* WV = (const float*)d_in[3];
    float* out = (float*)d_out;

    cudaFuncSetAttribute(proj_kernel,   cudaFuncAttributeMaxDynamicSharedMemorySize, SMEM_ALLOC);
    cudaFuncSetAttribute(scores_kernel, cudaFuncAttributeMaxDynamicSharedMemorySize, SMEM_ALLOC2);
    cudaFuncSetAttribute(pv_kernel,     cudaFuncAttributeMaxDynamicSharedMemorySize, SMEM_ALLOC2);

    convert_x_kernel<<<8192, 1024>>>(x);
    convert_w_kernel<<<768, 1024>>>(WQ, WK, WV);

    proj_kernel<<<dim3(4, 128, 3), NTHR, SMEM_ALLOC>>>();

    transpose_v_kernel<<<dim3(16, 128, 4), dim3(32, 8)>>>();

    scores_kernel<<<dim3(32, 32, 4), NTHR, SMEM_ALLOC2>>>();

    softmax_kernel<<<BATCH * SEQ, 256>>>();

    pv_kernel<<<dim3(4, 32, 4), NTHR, SMEM_ALLOC2>>>(out);
}

// round 8
// speedup vs baseline: 2.8301x; 1.3720x over previous
#include <cuda_runtime.h>
#include <cuda_bf16.h>
#include <cuda_fp16.h>
#include <cstdint>

#define BATCH 4
#define SEQ   4096
#define DIM   512

#define NSD (4ull*4096ull*512ull)     // 8,388,608
#define NW  (3ull*512ull*512ull)      // 786,432
#define NSS (4ull*4096ull*4096ull)    // 67,108,864

// ---------------- static scratch (allocation-free) ----------------
// proj inputs (bf16x3 path)
__device__ __nv_bfloat16 g_Xh[NSD], g_Xl[NSD];
__device__ __nv_bfloat16 g_Wh[NW],  g_Wl[NW];
// fp16 attention operands (all plain fp16 now)
__device__ __half g_Qf[NSD];
__device__ __half g_Kf[NSD];
__device__ __half g_Vf[NSD];
__device__ __half g_VTf[NSD];
__device__ float  g_P[NSS];
__device__ __half g_Ph[NSS];

// ---------------- PTX helpers (compute_103-baseline ISA only) ----------------
__device__ __forceinline__ uint32_t smem_u32(const void* p) {
    uint32_t a;
    asm("{ .reg .u64 t; cvta.to.shared.u64 t, %1; cvt.u32.u64 %0, t; }" : "=r"(a) : "l"(p));
    return a;
}

__device__ __forceinline__ void cp16(uint32_t s, const void* g) {
    asm volatile("cp.async.cg.shared.global [%0], [%1], 16;" :: "r"(s), "l"(g) : "memory");
}
#define CP_COMMIT() asm volatile("cp.async.commit_group;" ::: "memory")
#define CP_WAIT(n)  asm volatile("cp.async.wait_group %0;" :: "n"(n) : "memory")

__device__ __forceinline__ void ldm4(uint32_t addr, uint32_t r[4]) {
    asm volatile("ldmatrix.sync.aligned.m8n8.x4.shared.b16 {%0,%1,%2,%3}, [%4];"
                 : "=r"(r[0]), "=r"(r[1]), "=r"(r[2]), "=r"(r[3]) : "r"(addr));
}

__device__ __forceinline__ void mma_bf(float* c, const uint32_t* a, uint32_t b0, uint32_t b1) {
    asm volatile(
        "mma.sync.aligned.m16n8k16.row.col.f32.bf16.bf16.f32 "
        "{%0,%1,%2,%3}, {%4,%5,%6,%7}, {%8,%9}, {%0,%1,%2,%3};"
        : "+f"(c[0]), "+f"(c[1]), "+f"(c[2]), "+f"(c[3])
        : "r"(a[0]), "r"(a[1]), "r"(a[2]), "r"(a[3]), "r"(b0), "r"(b1));
}

__device__ __forceinline__ void mma_hf(float* c, const uint32_t* a, uint32_t b0, uint32_t b1) {
    asm volatile(
        "mma.sync.aligned.m16n8k16.row.col.f32.f16.f16.f32 "
        "{%0,%1,%2,%3}, {%4,%5,%6,%7}, {%8,%9}, {%0,%1,%2,%3};"
        : "+f"(c[0]), "+f"(c[1]), "+f"(c[2]), "+f"(c[3])
        : "r"(a[0]), "r"(a[1]), "r"(a[2]), "r"(a[3]), "r"(b0), "r"(b1));
}

// ---------------- GEMM config ----------------
// CTA tile 128x128, 256 thr = 8 warps (2 M x 4 N), warp tile 64x32.
// K-chunk 64 (128B data + 16B pad per row -> conflict-free ldmatrix).
#define ROWP     144
#define TILE_B   (128 * ROWP)          // 18432
// bf16x3 (proj): 4 tiles per stage
#define OFF_AH   0
#define OFF_AL   (1 * TILE_B)
#define OFF_BH   (2 * TILE_B)
#define OFF_BL   (3 * TILE_B)
#define STAGE_B  (4 * TILE_B)          // 73728
#define SMEM_ALLOC (2 * STAGE_B)       // 147456
// plain fp16 (scores/pv): 2 tiles per stage
#define OFF3_A   0
#define OFF3_B   (1 * TILE_B)
#define STAGE3_B (2 * TILE_B)          // 36864
#define SMEM_ALLOC3 (2 * STAGE3_B)     // 73728
#define NTHR     256

// one 128x64-elem (2B) tile -> smem (16B chunks, 8 per row); 256 threads
template <typename T>
__device__ __forceinline__ void fill_tile(uint32_t sb, const T* __restrict__ src,
                                          int ld, int k0, int tid) {
#pragma unroll
    for (int v = 0; v < 4; ++v) {
        int idx = v * NTHR + tid;         // 0..1023
        int row = idx >> 3;               // 0..127
        int c16 = idx & 7;                // 0..7
        cp16(sb + row * ROWP + c16 * 16, src + (size_t)row * ld + k0 + c16 * 8);
    }
}

// ---------------- bf16x3 mainloop (proj only) ----------------
__device__ __forceinline__ void gemm_bf16x3(
    const __nv_bfloat16* __restrict__ Ah, const __nv_bfloat16* __restrict__ Al, int lda,
    const __nv_bfloat16* __restrict__ Bh, const __nv_bfloat16* __restrict__ Bl, int ldb,
    int ktotal, float acc[4][4][4])
{
    extern __shared__ char rawsm[];
    const uint32_t smb = smem_u32(rawsm);
    const int tid  = threadIdx.x;
    const int lane = tid & 31;
    const int wid  = tid >> 5;
    const int wm   = wid >> 2;
    const int wn   = wid & 3;

#pragma unroll
    for (int i = 0; i < 4; ++i)
#pragma unroll
        for (int j = 0; j < 4; ++j)
#pragma unroll
            for (int k = 0; k < 4; ++k) acc[i][j][k] = 0.f;

    const int nch = ktotal >> 6;

    fill_tile(smb + OFF_AH, Ah, lda, 0, tid);
    fill_tile(smb + OFF_AL, Al, lda, 0, tid);
    fill_tile(smb + OFF_BH, Bh, ldb, 0, tid);
    fill_tile(smb + OFF_BL, Bl, ldb, 0, tid);
    CP_COMMIT();

    const uint32_t a_row_off = (uint32_t)((wm * 64 + (lane & 15)) * ROWP);
    const uint32_t b_row_off = (uint32_t)((wn * 32 + (lane & 7) + ((lane >> 3) & 1) * 8) * ROWP);
    const uint32_t k_half    = (uint32_t)(((lane >> 4) & 1) * 16);

    for (int c = 0; c < nch; ++c) {
        CP_WAIT(0);
        __syncthreads();
        if (c + 1 < nch) {
            const uint32_t nb = smb + (uint32_t)(((c + 1) & 1) * STAGE_B);
            const int nk = (c + 1) << 6;
            fill_tile(nb + OFF_AH, Ah, lda, nk, tid);
            fill_tile(nb + OFF_AL, Al, lda, nk, tid);
            fill_tile(nb + OFF_BH, Bh, ldb, nk, tid);
            fill_tile(nb + OFF_BL, Bl, ldb, nk, tid);
            CP_COMMIT();
        }

        const uint32_t sb = smb + (uint32_t)((c & 1) * STAGE_B);

#pragma unroll
        for (int ks = 0; ks < 4; ++ks) {
            const uint32_t ko = (uint32_t)(ks * 32) + k_half;

            uint32_t ra_h[4][4], ra_l[4][4], rb_h[2][4], rb_l[2][4];
#pragma unroll
            for (int mf = 0; mf < 4; ++mf) {
                ldm4(sb + OFF_AH + a_row_off + (uint32_t)(mf * 16 * ROWP) + ko, ra_h[mf]);
                ldm4(sb + OFF_AL + a_row_off + (uint32_t)(mf * 16 * ROWP) + ko, ra_l[mf]);
            }
#pragma unroll
            for (int bf = 0; bf < 2; ++bf) {
                ldm4(sb + OFF_BH + b_row_off + (uint32_t)(bf * 16 * ROWP) + ko, rb_h[bf]);
                ldm4(sb + OFF_BL + b_row_off + (uint32_t)(bf * 16 * ROWP) + ko, rb_l[bf]);
            }
#pragma unroll
            for (int mf = 0; mf < 4; ++mf)
#pragma unroll
                for (int bf = 0; bf < 2; ++bf) {
                    mma_bf(acc[mf][bf * 2],     ra_h[mf], rb_h[bf][0], rb_h[bf][2]);
                    mma_bf(acc[mf][bf * 2 + 1], ra_h[mf], rb_h[bf][1], rb_h[bf][3]);
                }
#pragma unroll
            for (int mf = 0; mf < 4; ++mf)
#pragma unroll
                for (int bf = 0; bf < 2; ++bf) {
                    mma_bf(acc[mf][bf * 2],     ra_h[mf], rb_l[bf][0], rb_l[bf][2]);
                    mma_bf(acc[mf][bf * 2 + 1], ra_h[mf], rb_l[bf][1], rb_l[bf][3]);
                }
#pragma unroll
            for (int mf = 0; mf < 4; ++mf)
#pragma unroll
                for (int bf = 0; bf < 2; ++bf) {
                    mma_bf(acc[mf][bf * 2],     ra_l[mf], rb_h[bf][0], rb_h[bf][2]);
                    mma_bf(acc[mf][bf * 2 + 1], ra_l[mf], rb_h[bf][1], rb_h[bf][3]);
                }
        }
    }
    __syncthreads();
}

// ---------------- plain fp16 mainloop (scores & pv) ----------------
__device__ __forceinline__ void gemm_fp16(
    const __half* __restrict__ A, int lda,
    const __half* __restrict__ B, int ldb,
    int ktotal, float acc[4][4][4])
{
    extern __shared__ char rawsm[];
    const uint32_t smb = smem_u32(rawsm);
    const int tid  = threadIdx.x;
    const int lane = tid & 31;
    const int wid  = tid >> 5;
    const int wm   = wid >> 2;
    const int wn   = wid & 3;

#pragma unroll
    for (int i = 0; i < 4; ++i)
#pragma unroll
        for (int j = 0; j < 4; ++j)
#pragma unroll
            for (int k = 0; k < 4; ++k) acc[i][j][k] = 0.f;

    const int nch = ktotal >> 6;

    fill_tile(smb + OFF3_A, A, lda, 0, tid);
    fill_tile(smb + OFF3_B, B, ldb, 0, tid);
    CP_COMMIT();

    const uint32_t a_row_off = (uint32_t)((wm * 64 + (lane & 15)) * ROWP);
    const uint32_t b_row_off = (uint32_t)((wn * 32 + (lane & 7) + ((lane >> 3) & 1) * 8) * ROWP);
    const uint32_t k_half    = (uint32_t)(((lane >> 4) & 1) * 16);

    for (int c = 0; c < nch; ++c) {
        CP_WAIT(0);
        __syncthreads();
        if (c + 1 < nch) {
            const uint32_t nb = smb + (uint32_t)(((c + 1) & 1) * STAGE3_B);
            const int nk = (c + 1) << 6;
            fill_tile(nb + OFF3_A, A, lda, nk, tid);
            fill_tile(nb + OFF3_B, B, ldb, nk, tid);
            CP_COMMIT();
        }

        const uint32_t sb = smb + (uint32_t)((c & 1) * STAGE3_B);

#pragma unroll
        for (int ks = 0; ks < 4; ++ks) {
            const uint32_t ko = (uint32_t)(ks * 32) + k_half;

            uint32_t ra[4][4], rb[2][4];
#pragma unroll
            for (int mf = 0; mf < 4; ++mf)
                ldm4(sb + OFF3_A + a_row_off + (uint32_t)(mf * 16 * ROWP) + ko, ra[mf]);
#pragma unroll
            for (int bf = 0; bf < 2; ++bf)
                ldm4(sb + OFF3_B + b_row_off + (uint32_t)(bf * 16 * ROWP) + ko, rb[bf]);

#pragma unroll
            for (int mf = 0; mf < 4; ++mf)
#pragma unroll
                for (int bf = 0; bf < 2; ++bf) {
                    mma_hf(acc[mf][bf * 2],     ra[mf], rb[bf][0], rb[bf][2]);
                    mma_hf(acc[mf][bf * 2 + 1], ra[mf], rb[bf][1], rb[bf][3]);
                }
        }
    }
    __syncthreads();
}

// ---------------- stage kernels ----------------

__global__ __launch_bounds__(1024) void convert_x_kernel(const float* __restrict__ x) {
    size_t i = (size_t)blockIdx.x * blockDim.x + threadIdx.x;
    if (i >= NSD) return;
    float v = x[i];
    __nv_bfloat16 h = __float2bfloat16(v);
    g_Xh[i] = h;
    g_Xl[i] = __float2bfloat16(v - __bfloat162float(h));
}

__global__ __launch_bounds__(1024) void convert_w_kernel(const float* __restrict__ wq,
                                                         const float* __restrict__ wk,
                                                         const float* __restrict__ wv) {
    size_t i = (size_t)blockIdx.x * blockDim.x + threadIdx.x;
    if (i >= NW) return;
    size_t which = i >> 18;
    size_t off   = i & 262143ull;
    const float* src = (which == 0) ? wq : (which == 1) ? wk : wv;
    float v = src[off];
    __nv_bfloat16 h = __float2bfloat16(v);
    g_Wh[i] = h;
    g_Wl[i] = __float2bfloat16(v - __bfloat162float(h));
}

// QKV projection (bf16x3): grid (4 ntile, 128 mtile, 3 which) -> plain fp16 outputs
__global__ __launch_bounds__(NTHR) void proj_kernel() {
    const int nt = blockIdx.x, mt = blockIdx.y, z = blockIdx.z;
    const __nv_bfloat16* Ah = g_Xh + (size_t)mt * 128 * DIM;
    const __nv_bfloat16* Al = g_Xl + (size_t)mt * 128 * DIM;
    const __nv_bfloat16* Bh = g_Wh + (size_t)z * DIM * DIM + (size_t)nt * 128 * DIM;
    const __nv_bfloat16* Bl = g_Wl + (size_t)z * DIM * DIM + (size_t)nt * 128 * DIM;

    float acc[4][4][4];
    gemm_bf16x3(Ah, Al, DIM, Bh, Bl, DIM, DIM, acc);

    __half* dst0 = (z == 0) ? g_Qf : (z == 1) ? g_Kf : g_Vf;

    const int lane = threadIdx.x & 31, wid = threadIdx.x >> 5;
    const int wm = wid >> 2, wn = wid & 3;
    const int g = lane >> 2, t = lane & 3;
    const size_t rbase = (size_t)mt * 128;
    const int cbase = nt * 128 + wn * 32 + 2 * t;

#pragma unroll
    for (int mf = 0; mf < 4; ++mf) {
#pragma unroll
        for (int nf = 0; nf < 4; ++nf) {
            const int col = cbase + nf * 8;
#pragma unroll
            for (int half = 0; half < 2; ++half) {
                const int row = wm * 64 + mf * 16 + g + half * 8;
                float v0 = acc[mf][nf][half * 2];
                float v1 = acc[mf][nf][half * 2 + 1];
                size_t o = (rbase + row) * DIM + col;
                *reinterpret_cast<__half2*>(dst0 + o) =
                    __halves2half2(__float2half_rn(v0), __float2half_rn(v1));
            }
        }
    }
}

// Transpose V (per batch) -> VT [D, S], fp16
__global__ __launch_bounds__(256) void transpose_v_kernel() {
    __shared__ __half th[32][33];
    const int b = blockIdx.z;
    const int d0 = blockIdx.x * 32, s0 = blockIdx.y * 32;
    const int tx = threadIdx.x, ty = threadIdx.y;
#pragma unroll
    for (int rr = ty; rr < 32; rr += 8) {
        size_t src = ((size_t)b * SEQ + s0 + rr) * DIM + d0 + tx;
        th[rr][tx] = g_Vf[src];
    }
    __syncthreads();
#pragma unroll
    for (int rr = ty; rr < 32; rr += 8) {
        size_t dst = ((size_t)b * DIM + d0 + rr) * SEQ + s0 + tx;
        g_VTf[dst] = th[tx][rr];
    }
}

// Scores (plain fp16): grid (32 kt, 32 qt, 4 b), skip kt > qt
__global__ __launch_bounds__(NTHR) void scores_kernel() {
    const int kt = blockIdx.x, qt = blockIdx.y, b = blockIdx.z;
    if (kt > qt) return;

    const size_t qoff = ((size_t)b * SEQ + (size_t)qt * 128) * DIM;
    const size_t koff = ((size_t)b * SEQ + (size_t)kt * 128) * DIM;

    float acc[4][4][4];
    gemm_fp16(g_Qf + qoff, DIM, g_Kf + koff, DIM, DIM, acc);

    const int lane = threadIdx.x & 31, wid = threadIdx.x >> 5;
    const int wm = wid >> 2, wn = wid & 3;
    const int g = lane >> 2, t = lane & 3;
    const float scale = 0.04419417382415922f;   // 1/sqrt(512)

#pragma unroll
    for (int mf = 0; mf < 4; ++mf) {
#pragma unroll
        for (int nf = 0; nf < 4; ++nf) {
            const int col = kt * 128 + wn * 32 + nf * 8 + 2 * t;
#pragma unroll
            for (int half = 0; half < 2; ++half) {
                const int qrow = qt * 128 + wm * 64 + mf * 16 + g + half * 8;
                float v0 = (col     <= qrow) ? acc[mf][nf][half * 2]     * scale : -1e30f;
                float v1 = (col + 1 <= qrow) ? acc[mf][nf][half * 2 + 1] * scale : -1e30f;
                float* dst = g_P + ((size_t)b * SEQ + qrow) * SEQ + col;
                *reinterpret_cast<float2*>(dst) = make_float2(v0, v1);
            }
        }
    }
}

// Row softmax over [0, jend): one gmem read, row cached in registers.
__global__ __launch_bounds__(256) void softmax_kernel() {
    const int rr = blockIdx.x;
    const int b = rr >> 12;
    const int i = rr & 4095;
    const size_t rowoff = ((size_t)b * SEQ + i) * SEQ;
    const float* row = g_P + rowoff;
    const int jend = ((i >> 7) + 1) << 7;

    const int tid = threadIdx.x, lane = tid & 31, wid = tid >> 5;
    __shared__ float red[8];

    float v[16];
    int cnt = 0;
    float m = -1e30f;
    for (int j = tid; j < jend; j += 256) {
        float x = row[j];
        v[cnt++] = x;
        m = fmaxf(m, x);
    }
#pragma unroll
    for (int o = 16; o > 0; o >>= 1) m = fmaxf(m, __shfl_xor_sync(0xffffffffu, m, o));
    if (lane == 0) red[wid] = m;
    __syncthreads();
    m = red[0];
#pragma unroll
    for (int w = 1; w < 8; w++) m = fmaxf(m, red[w]);

    float s = 0.f;
    for (int k = 0; k < cnt; ++k) {
        float e = __expf(v[k] - m);
        v[k] = e;
        s += e;
    }
#pragma unroll
    for (int o = 16; o > 0; o >>= 1) s += __shfl_xor_sync(0xffffffffu, s, o);
    __syncthreads();
    if (lane == 0) red[wid] = s;
    __syncthreads();
    s = red[0];
#pragma unroll
    for (int w = 1; w < 8; w++) s += red[w];

    const float inv = 1.0f / s;
    cnt = 0;
    for (int j = tid; j < jend; j += 256)
        g_Ph[rowoff + j] = __float2half_rn(v[cnt++] * inv);
}

// PV (plain fp16): grid (4 ntile, 32 qt, 4 b), K bounded by causal extent
__global__ __launch_bounds__(NTHR) void pv_kernel(float* __restrict__ out) {
    const int nt = blockIdx.x, qt = blockIdx.y, b = blockIdx.z;

    const size_t poff = ((size_t)b * SEQ + (size_t)qt * 128) * SEQ;
    const size_t voff = ((size_t)b * DIM + (size_t)nt * 128) * SEQ;
    const int kmax = (qt + 1) * 128;

    float acc[4][4][4];
    gemm_fp16(g_Ph + poff, SEQ, g_VTf + voff, SEQ, kmax, acc);

    const int lane = threadIdx.x & 31, wid = threadIdx.x >> 5;
    const int wm = wid >> 2, wn = wid & 3;
    const int g = lane >> 2, t = lane & 3;

#pragma unroll
    for (int mf = 0; mf < 4; ++mf) {
#pragma unroll
        for (int nf = 0; nf < 4; ++nf) {
            const int col = nt * 128 + wn * 32 + nf * 8 + 2 * t;
#pragma unroll
            for (int half = 0; half < 2; ++half) {
                const int row = qt * 128 + wm * 64 + mf * 16 + g + half * 8;
                float* dst = out + ((size_t)b * SEQ + row) * DIM + col;
                *reinterpret_cast<float2*>(dst) =
                    make_float2(acc[mf][nf][half * 2], acc[mf][nf][half * 2 + 1]);
            }
        }
    }
}

// ---------------- launch ----------------
extern "C" void kernel_launch(void* const* d_in, const int* in_sizes, int n_in,
                              void* d_out, int out_size)
{
    const float* x  = (const float*)d_in[0];
    const float* WQ = (const float*)d_in[1];
    const float* WK = (const float*)d_in[2];
    const float* WV = (const float*)d_in[3];
    float* out = (float*)d_out;

    cudaFuncSetAttribute(proj_kernel,   cudaFuncAttributeMaxDynamicSharedMemorySize, SMEM_ALLOC);
    cudaFuncSetAttribute(scores_kernel, cudaFuncAttributeMaxDynamicSharedMemorySize, SMEM_ALLOC3);
    cudaFuncSetAttribute(pv_kernel,     cudaFuncAttributeMaxDynamicSharedMemorySize, SMEM_ALLOC3);

    convert_x_kernel<<<8192, 1024>>>(x);
    convert_w_kernel<<<768, 1024>>>(WQ, WK, WV);

    proj_kernel<<<dim3(4, 128, 3), NTHR, SMEM_ALLOC>>>();

    transpose_v_kernel<<<dim3(16, 128, 4), dim3(32, 8)>>>();

    scores_kernel<<<dim3(32, 32, 4), NTHR, SMEM_ALLOC3>>>();

    softmax_kernel<<<BATCH * SEQ, 256>>>();

    pv_kernel<<<dim3(4, 32, 4), NTHR, SMEM_ALLOC3>>>(out);
}

// round 9
// speedup vs baseline: 3.3318x; 1.1773x over previous
#include <cuda_runtime.h>
#include <cuda_fp16.h>
#include <cstdint>

#define BATCH 4
#define SEQ   4096
#define DIM   512

#define NSD (4ull*4096ull*512ull)     // 8,388,608
#define NW  (3ull*512ull*512ull)      // 786,432
#define NSS (4ull*4096ull*4096ull)    // 67,108,864

// ---------------- static scratch (allocation-free) ----------------
__device__ __half g_Xh[NSD], g_Xl[NSD];      // X split fp16 hi/lo
__device__ __half g_Wf[NW];                  // weights plain fp16
__device__ __half g_Qf[NSD];
__device__ __half g_Kf[NSD];
__device__ __half g_Vf[NSD];
__device__ __half g_VTf[NSD];
__device__ float  g_P[NSS];
__device__ __half g_Ph[NSS];

// ---------------- PTX helpers (compute_103-baseline ISA only) ----------------
__device__ __forceinline__ uint32_t smem_u32(const void* p) {
    uint32_t a;
    asm("{ .reg .u64 t; cvta.to.shared.u64 t, %1; cvt.u32.u64 %0, t; }" : "=r"(a) : "l"(p));
    return a;
}

__device__ __forceinline__ void cp16(uint32_t s, const void* g) {
    asm volatile("cp.async.cg.shared.global [%0], [%1], 16;" :: "r"(s), "l"(g) : "memory");
}
#define CP_COMMIT() asm volatile("cp.async.commit_group;" ::: "memory")
#define CP_WAIT(n)  asm volatile("cp.async.wait_group %0;" :: "n"(n) : "memory")

__device__ __forceinline__ void ldm4(uint32_t addr, uint32_t r[4]) {
    asm volatile("ldmatrix.sync.aligned.m8n8.x4.shared.b16 {%0,%1,%2,%3}, [%4];"
                 : "=r"(r[0]), "=r"(r[1]), "=r"(r[2]), "=r"(r[3]) : "r"(addr));
}

__device__ __forceinline__ void mma_hf(float* c, const uint32_t* a, uint32_t b0, uint32_t b1) {
    asm volatile(
        "mma.sync.aligned.m16n8k16.row.col.f32.f16.f16.f32 "
        "{%0,%1,%2,%3}, {%4,%5,%6,%7}, {%8,%9}, {%0,%1,%2,%3};"
        : "+f"(c[0]), "+f"(c[1]), "+f"(c[2]), "+f"(c[3])
        : "r"(a[0]), "r"(a[1]), "r"(a[2]), "r"(a[3]), "r"(b0), "r"(b1));
}

// ---------------- GEMM config ----------------
// CTA tile 128x128, 256 thr = 8 warps (2 M x 4 N), warp tile 64x32.
// K-chunk 64 (128B data + 16B pad per row -> conflict-free ldmatrix).
#define ROWP     144
#define TILE_B   (128 * ROWP)          // 18432
// fp16x2 (proj): A-hi, A-lo, B -> 3 tiles per stage
#define OFF2_AH  0
#define OFF2_AL  (1 * TILE_B)
#define OFF2_B   (2 * TILE_B)
#define STAGE2_B (3 * TILE_B)          // 55296
#define SMEM_ALLOC2 (2 * STAGE2_B)     // 110592
// plain fp16 (scores/pv): 2 tiles per stage
#define OFF3_A   0
#define OFF3_B   (1 * TILE_B)
#define STAGE3_B (2 * TILE_B)          // 36864
#define SMEM_ALLOC3 (2 * STAGE3_B)     // 73728
#define NTHR     256

// one 128x64-elem (2B) tile -> smem (16B chunks, 8 per row); 256 threads
template <typename T>
__device__ __forceinline__ void fill_tile(uint32_t sb, const T* __restrict__ src,
                                          int ld, int k0, int tid) {
#pragma unroll
    for (int v = 0; v < 4; ++v) {
        int idx = v * NTHR + tid;         // 0..1023
        int row = idx >> 3;               // 0..127
        int c16 = idx & 7;                // 0..7
        cp16(sb + row * ROWP + c16 * 16, src + (size_t)row * ld + k0 + c16 * 8);
    }
}

// ---------------- fp16x2 mainloop (proj): A split, B plain ----------------
__device__ __forceinline__ void gemm_fp16x2(
    const __half* __restrict__ Ah, const __half* __restrict__ Al, int lda,
    const __half* __restrict__ B, int ldb,
    int ktotal, float acc[4][4][4])
{
    extern __shared__ char rawsm[];
    const uint32_t smb = smem_u32(rawsm);
    const int tid  = threadIdx.x;
    const int lane = tid & 31;
    const int wid  = tid >> 5;
    const int wm   = wid >> 2;
    const int wn   = wid & 3;

#pragma unroll
    for (int i = 0; i < 4; ++i)
#pragma unroll
        for (int j = 0; j < 4; ++j)
#pragma unroll
            for (int k = 0; k < 4; ++k) acc[i][j][k] = 0.f;

    const int nch = ktotal >> 6;

    fill_tile(smb + OFF2_AH, Ah, lda, 0, tid);
    fill_tile(smb + OFF2_AL, Al, lda, 0, tid);
    fill_tile(smb + OFF2_B,  B,  ldb, 0, tid);
    CP_COMMIT();

    const uint32_t a_row_off = (uint32_t)((wm * 64 + (lane & 15)) * ROWP);
    const uint32_t b_row_off = (uint32_t)((wn * 32 + (lane & 7) + ((lane >> 3) & 1) * 8) * ROWP);
    const uint32_t k_half    = (uint32_t)(((lane >> 4) & 1) * 16);

    for (int c = 0; c < nch; ++c) {
        CP_WAIT(0);
        __syncthreads();
        if (c + 1 < nch) {
            const uint32_t nb = smb + (uint32_t)(((c + 1) & 1) * STAGE2_B);
            const int nk = (c + 1) << 6;
            fill_tile(nb + OFF2_AH, Ah, lda, nk, tid);
            fill_tile(nb + OFF2_AL, Al, lda, nk, tid);
            fill_tile(nb + OFF2_B,  B,  ldb, nk, tid);
            CP_COMMIT();
        }

        const uint32_t sb = smb + (uint32_t)((c & 1) * STAGE2_B);

#pragma unroll
        for (int ks = 0; ks < 4; ++ks) {
            const uint32_t ko = (uint32_t)(ks * 32) + k_half;

            uint32_t ra_h[4][4], ra_l[4][4], rb[2][4];
#pragma unroll
            for (int mf = 0; mf < 4; ++mf) {
                ldm4(sb + OFF2_AH + a_row_off + (uint32_t)(mf * 16 * ROWP) + ko, ra_h[mf]);
                ldm4(sb + OFF2_AL + a_row_off + (uint32_t)(mf * 16 * ROWP) + ko, ra_l[mf]);
            }
#pragma unroll
            for (int bf = 0; bf < 2; ++bf)
                ldm4(sb + OFF2_B + b_row_off + (uint32_t)(bf * 16 * ROWP) + ko, rb[bf]);

            // pass 1: Ah*B
#pragma unroll
            for (int mf = 0; mf < 4; ++mf)
#pragma unroll
                for (int bf = 0; bf < 2; ++bf) {
                    mma_hf(acc[mf][bf * 2],     ra_h[mf], rb[bf][0], rb[bf][2]);
                    mma_hf(acc[mf][bf * 2 + 1], ra_h[mf], rb[bf][1], rb[bf][3]);
                }
            // pass 2: Al*B
#pragma unroll
            for (int mf = 0; mf < 4; ++mf)
#pragma unroll
                for (int bf = 0; bf < 2; ++bf) {
                    mma_hf(acc[mf][bf * 2],     ra_l[mf], rb[bf][0], rb[bf][2]);
                    mma_hf(acc[mf][bf * 2 + 1], ra_l[mf], rb[bf][1], rb[bf][3]);
                }
        }
    }
    __syncthreads();
}

// ---------------- plain fp16 mainloop (scores & pv) ----------------
__device__ __forceinline__ void gemm_fp16(
    const __half* __restrict__ A, int lda,
    const __half* __restrict__ B, int ldb,
    int ktotal, float acc[4][4][4])
{
    extern __shared__ char rawsm[];
    const uint32_t smb = smem_u32(rawsm);
    const int tid  = threadIdx.x;
    const int lane = tid & 31;
    const int wid  = tid >> 5;
    const int wm   = wid >> 2;
    const int wn   = wid & 3;

#pragma unroll
    for (int i = 0; i < 4; ++i)
#pragma unroll
        for (int j = 0; j < 4; ++j)
#pragma unroll
            for (int k = 0; k < 4; ++k) acc[i][j][k] = 0.f;

    const int nch = ktotal >> 6;

    fill_tile(smb + OFF3_A, A, lda, 0, tid);
    fill_tile(smb + OFF3_B, B, ldb, 0, tid);
    CP_COMMIT();

    const uint32_t a_row_off = (uint32_t)((wm * 64 + (lane & 15)) * ROWP);
    const uint32_t b_row_off = (uint32_t)((wn * 32 + (lane & 7) + ((lane >> 3) & 1) * 8) * ROWP);
    const uint32_t k_half    = (uint32_t)(((lane >> 4) & 1) * 16);

    for (int c = 0; c < nch; ++c) {
        CP_WAIT(0);
        __syncthreads();
        if (c + 1 < nch) {
            const uint32_t nb = smb + (uint32_t)(((c + 1) & 1) * STAGE3_B);
            const int nk = (c + 1) << 6;
            fill_tile(nb + OFF3_A, A, lda, nk, tid);
            fill_tile(nb + OFF3_B, B, ldb, nk, tid);
            CP_COMMIT();
        }

        const uint32_t sb = smb + (uint32_t)((c & 1) * STAGE3_B);

#pragma unroll
        for (int ks = 0; ks < 4; ++ks) {
            const uint32_t ko = (uint32_t)(ks * 32) + k_half;

            uint32_t ra[4][4], rb[2][4];
#pragma unroll
            for (int mf = 0; mf < 4; ++mf)
                ldm4(sb + OFF3_A + a_row_off + (uint32_t)(mf * 16 * ROWP) + ko, ra[mf]);
#pragma unroll
            for (int bf = 0; bf < 2; ++bf)
                ldm4(sb + OFF3_B + b_row_off + (uint32_t)(bf * 16 * ROWP) + ko, rb[bf]);

#pragma unroll
            for (int mf = 0; mf < 4; ++mf)
#pragma unroll
                for (int bf = 0; bf < 2; ++bf) {
                    mma_hf(acc[mf][bf * 2],     ra[mf], rb[bf][0], rb[bf][2]);
                    mma_hf(acc[mf][bf * 2 + 1], ra[mf], rb[bf][1], rb[bf][3]);
                }
        }
    }
    __syncthreads();
}

// ---------------- stage kernels ----------------

// X -> fp16 hi/lo split
__global__ __launch_bounds__(1024) void convert_x_kernel(const float* __restrict__ x) {
    size_t i = (size_t)blockIdx.x * blockDim.x + threadIdx.x;
    if (i >= NSD) return;
    float v = x[i];
    __half h = __float2half_rn(v);
    g_Xh[i] = h;
    g_Xl[i] = __float2half_rn(v - __half2float(h));
}

// W -> plain fp16
__global__ __launch_bounds__(1024) void convert_w_kernel(const float* __restrict__ wq,
                                                         const float* __restrict__ wk,
                                                         const float* __restrict__ wv) {
    size_t i = (size_t)blockIdx.x * blockDim.x + threadIdx.x;
    if (i >= NW) return;
    size_t which = i >> 18;
    size_t off   = i & 262143ull;
    const float* src = (which == 0) ? wq : (which == 1) ? wk : wv;
    g_Wf[i] = __float2half_rn(src[off]);
}

// QKV projection (fp16x2): grid (4 ntile, 128 mtile, 3 which) -> plain fp16 outputs
__global__ __launch_bounds__(NTHR) void proj_kernel() {
    const int nt = blockIdx.x, mt = blockIdx.y, z = blockIdx.z;
    const __half* Ah = g_Xh + (size_t)mt * 128 * DIM;
    const __half* Al = g_Xl + (size_t)mt * 128 * DIM;
    const __half* B  = g_Wf + (size_t)z * DIM * DIM + (size_t)nt * 128 * DIM;

    float acc[4][4][4];
    gemm_fp16x2(Ah, Al, DIM, B, DIM, DIM, acc);

    __half* dst0 = (z == 0) ? g_Qf : (z == 1) ? g_Kf : g_Vf;

    const int lane = threadIdx.x & 31, wid = threadIdx.x >> 5;
    const int wm = wid >> 2, wn = wid & 3;
    const int g = lane >> 2, t = lane & 3;
    const size_t rbase = (size_t)mt * 128;
    const int cbase = nt * 128 + wn * 32 + 2 * t;

#pragma unroll
    for (int mf = 0; mf < 4; ++mf) {
#pragma unroll
        for (int nf = 0; nf < 4; ++nf) {
            const int col = cbase + nf * 8;
#pragma unroll
            for (int half = 0; half < 2; ++half) {
                const int row = wm * 64 + mf * 16 + g + half * 8;
                float v0 = acc[mf][nf][half * 2];
                float v1 = acc[mf][nf][half * 2 + 1];
                size_t o = (rbase + row) * DIM + col;
                *reinterpret_cast<__half2*>(dst0 + o) =
                    __halves2half2(__float2half_rn(v0), __float2half_rn(v1));
            }
        }
    }
}

// Transpose V (per batch) -> VT [D, S], fp16
__global__ __launch_bounds__(256) void transpose_v_kernel() {
    __shared__ __half th[32][33];
    const int b = blockIdx.z;
    const int d0 = blockIdx.x * 32, s0 = blockIdx.y * 32;
    const int tx = threadIdx.x, ty = threadIdx.y;
#pragma unroll
    for (int rr = ty; rr < 32; rr += 8) {
        size_t src = ((size_t)b * SEQ + s0 + rr) * DIM + d0 + tx;
        th[rr][tx] = g_Vf[src];
    }
    __syncthreads();
#pragma unroll
    for (int rr = ty; rr < 32; rr += 8) {
        size_t dst = ((size_t)b * DIM + d0 + rr) * SEQ + s0 + tx;
        g_VTf[dst] = th[tx][rr];
    }
}

// Scores (plain fp16): grid (32 kt, 32 qt, 4 b), skip kt > qt
__global__ __launch_bounds__(NTHR) void scores_kernel() {
    const int kt = blockIdx.x, qt = blockIdx.y, b = blockIdx.z;
    if (kt > qt) return;

    const size_t qoff = ((size_t)b * SEQ + (size_t)qt * 128) * DIM;
    const size_t koff = ((size_t)b * SEQ + (size_t)kt * 128) * DIM;

    float acc[4][4][4];
    gemm_fp16(g_Qf + qoff, DIM, g_Kf + koff, DIM, DIM, acc);

    const int lane = threadIdx.x & 31, wid = threadIdx.x >> 5;
    const int wm = wid >> 2, wn = wid & 3;
    const int g = lane >> 2, t = lane & 3;
    const float scale = 0.04419417382415922f;   // 1/sqrt(512)

#pragma unroll
    for (int mf = 0; mf < 4; ++mf) {
#pragma unroll
        for (int nf = 0; nf < 4; ++nf) {
            const int col = kt * 128 + wn * 32 + nf * 8 + 2 * t;
#pragma unroll
            for (int half = 0; half < 2; ++half) {
                const int qrow = qt * 128 + wm * 64 + mf * 16 + g + half * 8;
                float v0 = (col     <= qrow) ? acc[mf][nf][half * 2]     * scale : -1e30f;
                float v1 = (col + 1 <= qrow) ? acc[mf][nf][half * 2 + 1] * scale : -1e30f;
                float* dst = g_P + ((size_t)b * SEQ + qrow) * SEQ + col;
                *reinterpret_cast<float2*>(dst) = make_float2(v0, v1);
            }
        }
    }
}

// Row softmax over [0, jend): one gmem read, row cached in registers.
__global__ __launch_bounds__(256) void softmax_kernel() {
    const int rr = blockIdx.x;
    const int b = rr >> 12;
    const int i = rr & 4095;
    const size_t rowoff = ((size_t)b * SEQ + i) * SEQ;
    const float* row = g_P + rowoff;
    const int jend = ((i >> 7) + 1) << 7;

    const int tid = threadIdx.x, lane = tid & 31, wid = tid >> 5;
    __shared__ float red[8];

    float v[16];
    int cnt = 0;
    float m = -1e30f;
    for (int j = tid; j < jend; j += 256) {
        float x = row[j];
        v[cnt++] = x;
        m = fmaxf(m, x);
    }
#pragma unroll
    for (int o = 16; o > 0; o >>= 1) m = fmaxf(m, __shfl_xor_sync(0xffffffffu, m, o));
    if (lane == 0) red[wid] = m;
    __syncthreads();
    m = red[0];
#pragma unroll
    for (int w = 1; w < 8; w++) m = fmaxf(m, red[w]);

    float s = 0.f;
    for (int k = 0; k < cnt; ++k) {
        float e = __expf(v[k] - m);
        v[k] = e;
        s += e;
    }
#pragma unroll
    for (int o = 16; o > 0; o >>= 1) s += __shfl_xor_sync(0xffffffffu, s, o);
    __syncthreads();
    if (lane == 0) red[wid] = s;
    __syncthreads();
    s = red[0];
#pragma unroll
    for (int w = 1; w < 8; w++) s += red[w];

    const float inv = 1.0f / s;
    cnt = 0;
    for (int j = tid; j < jend; j += 256)
        g_Ph[rowoff + j] = __float2half_rn(v[cnt++] * inv);
}

// PV (plain fp16): grid (4 ntile, 32 qt, 4 b), K bounded by causal extent
__global__ __launch_bounds__(NTHR) void pv_kernel(float* __restrict__ out) {
    const int nt = blockIdx.x, qt = blockIdx.y, b = blockIdx.z;

    const size_t poff = ((size_t)b * SEQ + (size_t)qt * 128) * SEQ;
    const size_t voff = ((size_t)b * DIM + (size_t)nt * 128) * SEQ;
    const int kmax = (qt + 1) * 128;

    float acc[4][4][4];
    gemm_fp16(g_Ph + poff, SEQ, g_VTf + voff, SEQ, kmax, acc);

    const int lane = threadIdx.x & 31, wid = threadIdx.x >> 5;
    const int wm = wid >> 2, wn = wid & 3;
    const int g = lane >> 2, t = lane & 3;

#pragma unroll
    for (int mf = 0; mf < 4; ++mf) {
#pragma unroll
        for (int nf = 0; nf < 4; ++nf) {
            const int col = nt * 128 + wn * 32 + nf * 8 + 2 * t;
#pragma unroll
            for (int half = 0; half < 2; ++half) {
                const int row = qt * 128 + wm * 64 + mf * 16 + g + half * 8;
                float* dst = out + ((size_t)b * SEQ + row) * DIM + col;
                *reinterpret_cast<float2*>(dst) =
                    make_float2(acc[mf][nf][half * 2], acc[mf][nf][half * 2 + 1]);
            }
        }
    }
}

// ---------------- launch ----------------
extern "C" void kernel_launch(void* const* d_in, const int* in_sizes, int n_in,
                              void* d_out, int out_size)
{
    const float* x  = (const float*)d_in[0];
    const float* WQ = (const float*)d_in[1];
    const float* WK = (const float*)d_in[2];
    const float* WV = (const float*)d_in[3];
    float* out = (float*)d_out;

    cudaFuncSetAttribute(proj_kernel,   cudaFuncAttributeMaxDynamicSharedMemorySize, SMEM_ALLOC2);
    cudaFuncSetAttribute(scores_kernel, cudaFuncAttributeMaxDynamicSharedMemorySize, SMEM_ALLOC3);
    cudaFuncSetAttribute(pv_kernel,     cudaFuncAttributeMaxDynamicSharedMemorySize, SMEM_ALLOC3);

    convert_x_kernel<<<8192, 1024>>>(x);
    convert_w_kernel<<<768, 1024>>>(WQ, WK, WV);

    proj_kernel<<<dim3(4, 128, 3), NTHR, SMEM_ALLOC2>>>();

    transpose_v_kernel<<<dim3(16, 128, 4), dim3(32, 8)>>>();

    scores_kernel<<<dim3(32, 32, 4), NTHR, SMEM_ALLOC3>>>();

    softmax_kernel<<<BATCH * SEQ, 256>>>();

    pv_kernel<<<dim3(4, 32, 4), NTHR, SMEM_ALLOC3>>>(out);
}

// round 10
// speedup vs baseline: 3.7731x; 1.1324x over previous
#include <cuda_runtime.h>
#include <cuda_fp16.h>
#include <cstdint>

#define BATCH 4
#define SEQ   4096
#define DIM   512

#define NSD (4ull*4096ull*512ull)     // 8,388,608
#define NW  (3ull*512ull*512ull)      // 786,432
#define NSS (4ull*4096ull*4096ull)    // 67,108,864

// ---------------- static scratch (allocation-free) ----------------
__device__ __half g_Xf[NSD];                 // X plain fp16
__device__ __half g_Wf[NW];                  // weights plain fp16
__device__ __half g_Qf[NSD];
__device__ __half g_Kf[NSD];
__device__ __half g_Vf[NSD];
__device__ __half g_VTf[NSD];
__device__ float  g_P[NSS];
__device__ __half g_Ph[NSS];

// ---------------- PTX helpers (compute_103-baseline ISA only) ----------------
__device__ __forceinline__ uint32_t smem_u32(const void* p) {
    uint32_t a;
    asm("{ .reg .u64 t; cvta.to.shared.u64 t, %1; cvt.u32.u64 %0, t; }" : "=r"(a) : "l"(p));
    return a;
}

__device__ __forceinline__ void cp16(uint32_t s, const void* g) {
    asm volatile("cp.async.cg.shared.global [%0], [%1], 16;" :: "r"(s), "l"(g) : "memory");
}
#define CP_COMMIT() asm volatile("cp.async.commit_group;" ::: "memory")
#define CP_WAIT(n)  asm volatile("cp.async.wait_group %0;" :: "n"(n) : "memory")

__device__ __forceinline__ void ldm4(uint32_t addr, uint32_t r[4]) {
    asm volatile("ldmatrix.sync.aligned.m8n8.x4.shared.b16 {%0,%1,%2,%3}, [%4];"
                 : "=r"(r[0]), "=r"(r[1]), "=r"(r[2]), "=r"(r[3]) : "r"(addr));
}

__device__ __forceinline__ void mma_hf(float* c, const uint32_t* a, uint32_t b0, uint32_t b1) {
    asm volatile(
        "mma.sync.aligned.m16n8k16.row.col.f32.f16.f16.f32 "
        "{%0,%1,%2,%3}, {%4,%5,%6,%7}, {%8,%9}, {%0,%1,%2,%3};"
        : "+f"(c[0]), "+f"(c[1]), "+f"(c[2]), "+f"(c[3])
        : "r"(a[0]), "r"(a[1]), "r"(a[2]), "r"(a[3]), "r"(b0), "r"(b1));
}

// ---------------- GEMM config ----------------
// CTA tile 128x128, 256 thr = 8 warps (2 M x 4 N), warp tile 64x32.
// K-chunk 64 (128B data + 16B pad per row -> conflict-free ldmatrix).
#define ROWP     144
#define TILE_B   (128 * ROWP)          // 18432
// plain fp16: 2 tiles per stage, double buffered
#define OFF3_A   0
#define OFF3_B   (1 * TILE_B)
#define STAGE3_B (2 * TILE_B)          // 36864
#define SMEM_ALLOC3 (2 * STAGE3_B)     // 73728
#define NTHR     256

// one 128x64-elem (2B) tile -> smem (16B chunks, 8 per row); 256 threads
template <typename T>
__device__ __forceinline__ void fill_tile(uint32_t sb, const T* __restrict__ src,
                                          int ld, int k0, int tid) {
#pragma unroll
    for (int v = 0; v < 4; ++v) {
        int idx = v * NTHR + tid;         // 0..1023
        int row = idx >> 3;               // 0..127
        int c16 = idx & 7;                // 0..7
        cp16(sb + row * ROWP + c16 * 16, src + (size_t)row * ld + k0 + c16 * 8);
    }
}

// ---------------- plain fp16 mainloop (all GEMMs) ----------------
__device__ __forceinline__ void gemm_fp16(
    const __half* __restrict__ A, int lda,
    const __half* __restrict__ B, int ldb,
    int ktotal, float acc[4][4][4])
{
    extern __shared__ char rawsm[];
    const uint32_t smb = smem_u32(rawsm);
    const int tid  = threadIdx.x;
    const int lane = tid & 31;
    const int wid  = tid >> 5;
    const int wm   = wid >> 2;
    const int wn   = wid & 3;

#pragma unroll
    for (int i = 0; i < 4; ++i)
#pragma unroll
        for (int j = 0; j < 4; ++j)
#pragma unroll
            for (int k = 0; k < 4; ++k) acc[i][j][k] = 0.f;

    const int nch = ktotal >> 6;

    fill_tile(smb + OFF3_A, A, lda, 0, tid);
    fill_tile(smb + OFF3_B, B, ldb, 0, tid);
    CP_COMMIT();

    const uint32_t a_row_off = (uint32_t)((wm * 64 + (lane & 15)) * ROWP);
    const uint32_t b_row_off = (uint32_t)((wn * 32 + (lane & 7) + ((lane >> 3) & 1) * 8) * ROWP);
    const uint32_t k_half    = (uint32_t)(((lane >> 4) & 1) * 16);

    for (int c = 0; c < nch; ++c) {
        CP_WAIT(0);
        __syncthreads();
        if (c + 1 < nch) {
            const uint32_t nb = smb + (uint32_t)(((c + 1) & 1) * STAGE3_B);
            const int nk = (c + 1) << 6;
            fill_tile(nb + OFF3_A, A, lda, nk, tid);
            fill_tile(nb + OFF3_B, B, ldb, nk, tid);
            CP_COMMIT();
        }

        const uint32_t sb = smb + (uint32_t)((c & 1) * STAGE3_B);

#pragma unroll
        for (int ks = 0; ks < 4; ++ks) {
            const uint32_t ko = (uint32_t)(ks * 32) + k_half;

            uint32_t ra[4][4], rb[2][4];
#pragma unroll
            for (int mf = 0; mf < 4; ++mf)
                ldm4(sb + OFF3_A + a_row_off + (uint32_t)(mf * 16 * ROWP) + ko, ra[mf]);
#pragma unroll
            for (int bf = 0; bf < 2; ++bf)
                ldm4(sb + OFF3_B + b_row_off + (uint32_t)(bf * 16 * ROWP) + ko, rb[bf]);

#pragma unroll
            for (int mf = 0; mf < 4; ++mf)
#pragma unroll
                for (int bf = 0; bf < 2; ++bf) {
                    mma_hf(acc[mf][bf * 2],     ra[mf], rb[bf][0], rb[bf][2]);
                    mma_hf(acc[mf][bf * 2 + 1], ra[mf], rb[bf][1], rb[bf][3]);
                }
        }
    }
    __syncthreads();
}

// ---------------- stage kernels ----------------

// X -> plain fp16
__global__ __launch_bounds__(1024) void convert_x_kernel(const float* __restrict__ x) {
    size_t i = (size_t)blockIdx.x * blockDim.x + threadIdx.x;
    if (i >= NSD) return;
    g_Xf[i] = __float2half_rn(x[i]);
}

// W -> plain fp16
__global__ __launch_bounds__(1024) void convert_w_kernel(const float* __restrict__ wq,
                                                         const float* __restrict__ wk,
                                                         const float* __restrict__ wv) {
    size_t i = (size_t)blockIdx.x * blockDim.x + threadIdx.x;
    if (i >= NW) return;
    size_t which = i >> 18;
    size_t off   = i & 262143ull;
    const float* src = (which == 0) ? wq : (which == 1) ? wk : wv;
    g_Wf[i] = __float2half_rn(src[off]);
}

// QKV projection (plain fp16): grid (4 ntile, 128 mtile, 3 which)
__global__ __launch_bounds__(NTHR) void proj_kernel() {
    const int nt = blockIdx.x, mt = blockIdx.y, z = blockIdx.z;
    const __half* A = g_Xf + (size_t)mt * 128 * DIM;
    const __half* B = g_Wf + (size_t)z * DIM * DIM + (size_t)nt * 128 * DIM;

    float acc[4][4][4];
    gemm_fp16(A, DIM, B, DIM, DIM, acc);

    __half* dst0 = (z == 0) ? g_Qf : (z == 1) ? g_Kf : g_Vf;

    const int lane = threadIdx.x & 31, wid = threadIdx.x >> 5;
    const int wm = wid >> 2, wn = wid & 3;
    const int g = lane >> 2, t = lane & 3;
    const size_t rbase = (size_t)mt * 128;
    const int cbase = nt * 128 + wn * 32 + 2 * t;

#pragma unroll
    for (int mf = 0; mf < 4; ++mf) {
#pragma unroll
        for (int nf = 0; nf < 4; ++nf) {
            const int col = cbase + nf * 8;
#pragma unroll
            for (int half = 0; half < 2; ++half) {
                const int row = wm * 64 + mf * 16 + g + half * 8;
                float v0 = acc[mf][nf][half * 2];
                float v1 = acc[mf][nf][half * 2 + 1];
                size_t o = (rbase + row) * DIM + col;
                *reinterpret_cast<__half2*>(dst0 + o) =
                    __halves2half2(__float2half_rn(v0), __float2half_rn(v1));
            }
        }
    }
}

// Transpose V (per batch) -> VT [D, S], fp16
__global__ __launch_bounds__(256) void transpose_v_kernel() {
    __shared__ __half th[32][33];
    const int b = blockIdx.z;
    const int d0 = blockIdx.x * 32, s0 = blockIdx.y * 32;
    const int tx = threadIdx.x, ty = threadIdx.y;
#pragma unroll
    for (int rr = ty; rr < 32; rr += 8) {
        size_t src = ((size_t)b * SEQ + s0 + rr) * DIM + d0 + tx;
        th[rr][tx] = g_Vf[src];
    }
    __syncthreads();
#pragma unroll
    for (int rr = ty; rr < 32; rr += 8) {
        size_t dst = ((size_t)b * DIM + d0 + rr) * SEQ + s0 + tx;
        g_VTf[dst] = th[tx][rr];
    }
}

// Scores (plain fp16): grid (32 kt, 32 qt, 4 b), skip kt > qt
__global__ __launch_bounds__(NTHR) void scores_kernel() {
    const int kt = blockIdx.x, qt = blockIdx.y, b = blockIdx.z;
    if (kt > qt) return;

    const size_t qoff = ((size_t)b * SEQ + (size_t)qt * 128) * DIM;
    const size_t koff = ((size_t)b * SEQ + (size_t)kt * 128) * DIM;

    float acc[4][4][4];
    gemm_fp16(g_Qf + qoff, DIM, g_Kf + koff, DIM, DIM, acc);

    const int lane = threadIdx.x & 31, wid = threadIdx.x >> 5;
    const int wm = wid >> 2, wn = wid & 3;
    const int g = lane >> 2, t = lane & 3;
    const float scale = 0.04419417382415922f;   // 1/sqrt(512)

#pragma unroll
    for (int mf = 0; mf < 4; ++mf) {
#pragma unroll
        for (int nf = 0; nf < 4; ++nf) {
            const int col = kt * 128 + wn * 32 + nf * 8 + 2 * t;
#pragma unroll
            for (int half = 0; half < 2; ++half) {
                const int qrow = qt * 128 + wm * 64 + mf * 16 + g + half * 8;
                float v0 = (col     <= qrow) ? acc[mf][nf][half * 2]     * scale : -1e30f;
                float v1 = (col + 1 <= qrow) ? acc[mf][nf][half * 2 + 1] * scale : -1e30f;
                float* dst = g_P + ((size_t)b * SEQ + qrow) * SEQ + col;
                *reinterpret_cast<float2*>(dst) = make_float2(v0, v1);
            }
        }
    }
}

// Row softmax over [0, jend): one gmem read, row cached in registers.
__global__ __launch_bounds__(256) void softmax_kernel() {
    const int rr = blockIdx.x;
    const int b = rr >> 12;
    const int i = rr & 4095;
    const size_t rowoff = ((size_t)b * SEQ + i) * SEQ;
    const float* row = g_P + rowoff;
    const int jend = ((i >> 7) + 1) << 7;

    const int tid = threadIdx.x, lane = tid & 31, wid = tid >> 5;
    __shared__ float red[8];

    float v[16];
    int cnt = 0;
    float m = -1e30f;
    for (int j = tid; j < jend; j += 256) {
        float x = row[j];
        v[cnt++] = x;
        m = fmaxf(m, x);
    }
#pragma unroll
    for (int o = 16; o > 0; o >>= 1) m = fmaxf(m, __shfl_xor_sync(0xffffffffu, m, o));
    if (lane == 0) red[wid] = m;
    __syncthreads();
    m = red[0];
#pragma unroll
    for (int w = 1; w < 8; w++) m = fmaxf(m, red[w]);

    float s = 0.f;
    for (int k = 0; k < cnt; ++k) {
        float e = __expf(v[k] - m);
        v[k] = e;
        s += e;
    }
#pragma unroll
    for (int o = 16; o > 0; o >>= 1) s += __shfl_xor_sync(0xffffffffu, s, o);
    __syncthreads();
    if (lane == 0) red[wid] = s;
    __syncthreads();
    s = red[0];
#pragma unroll
    for (int w = 1; w < 8; w++) s += red[w];

    const float inv = 1.0f / s;
    cnt = 0;
    for (int j = tid; j < jend; j += 256)
        g_Ph[rowoff + j] = __float2half_rn(v[cnt++] * inv);
}

// PV (plain fp16): grid (4 ntile, 32 qt, 4 b), K bounded by causal extent
__global__ __launch_bounds__(NTHR) void pv_kernel(float* __restrict__ out) {
    const int nt = blockIdx.x, qt = blockIdx.y, b = blockIdx.z;

    const size_t poff = ((size_t)b * SEQ + (size_t)qt * 128) * SEQ;
    const size_t voff = ((size_t)b * DIM + (size_t)nt * 128) * SEQ;
    const int kmax = (qt + 1) * 128;

    float acc[4][4][4];
    gemm_fp16(g_Ph + poff, SEQ, g_VTf + voff, SEQ, kmax, acc);

    const int lane = threadIdx.x & 31, wid = threadIdx.x >> 5;
    const int wm = wid >> 2, wn = wid & 3;
    const int g = lane >> 2, t = lane & 3;

#pragma unroll
    for (int mf = 0; mf < 4; ++mf) {
#pragma unroll
        for (int nf = 0; nf < 4; ++nf) {
            const int col = nt * 128 + wn * 32 + nf * 8 + 2 * t;
#pragma unroll
            for (int half = 0; half < 2; ++half) {
                const int row = qt * 128 + wm * 64 + mf * 16 + g + half * 8;
                float* dst = out + ((size_t)b * SEQ + row) * DIM + col;
                *reinterpret_cast<float2*>(dst) =
                    make_float2(acc[mf][nf][half * 2], acc[mf][nf][half * 2 + 1]);
            }
        }
    }
}

// ---------------- launch ----------------
extern "C" void kernel_launch(void* const* d_in, const int* in_sizes, int n_in,
                              void* d_out, int out_size)
{
    const float* x  = (const float*)d_in[0];
    const float* WQ = (const float*)d_in[1];
    const float* WK = (const float*)d_in[2];
    const float* WV = (const float*)d_in[3];
    float* out = (float*)d_out;

    cudaFuncSetAttribute(proj_kernel,   cudaFuncAttributeMaxDynamicSharedMemorySize, SMEM_ALLOC3);
    cudaFuncSetAttribute(scores_kernel, cudaFuncAttributeMaxDynamicSharedMemorySize, SMEM_ALLOC3);
    cudaFuncSetAttribute(pv_kernel,     cudaFuncAttributeMaxDynamicSharedMemorySize, SMEM_ALLOC3);

    convert_x_kernel<<<8192, 1024>>>(x);
    convert_w_kernel<<<768, 1024>>>(WQ, WK, WV);

    proj_kernel<<<dim3(4, 128, 3), NTHR, SMEM_ALLOC3>>>();

    transpose_v_kernel<<<dim3(16, 128, 4), dim3(32, 8)>>>();

    scores_kernel<<<dim3(32, 32, 4), NTHR, SMEM_ALLOC3>>>();

    softmax_kernel<<<BATCH * SEQ, 256>>>();

    pv_kernel<<<dim3(4, 32, 4), NTHR, SMEM_ALLOC3>>>(out);
}

// round 11
// speedup vs baseline: 3.8673x; 1.0250x over previous
#include <cuda_runtime.h>
#include <cuda_fp16.h>
#include <cstdint>

#define BATCH 4
#define SEQ   4096
#define DIM   512

#define NSD (4ull*4096ull*512ull)     // 8,388,608
#define NW  (3ull*512ull*512ull)      // 786,432
#define NSS (4ull*4096ull*4096ull)    // 67,108,864

// ---------------- static scratch (allocation-free) ----------------
__device__ __half g_Xf[NSD];                 // X plain fp16
__device__ __half g_Wf[NW];                  // weights plain fp16
__device__ __half g_Qf[NSD];
__device__ __half g_Kf[NSD];
__device__ __half g_Vf[NSD];
__device__ float  g_P[NSS];
__device__ __half g_Ph[NSS];

// ---------------- PTX helpers (compute_103-baseline ISA only) ----------------
__device__ __forceinline__ uint32_t smem_u32(const void* p) {
    uint32_t a;
    asm("{ .reg .u64 t; cvta.to.shared.u64 t, %1; cvt.u32.u64 %0, t; }" : "=r"(a) : "l"(p));
    return a;
}

__device__ __forceinline__ void cp16(uint32_t s, const void* g) {
    asm volatile("cp.async.cg.shared.global [%0], [%1], 16;" :: "r"(s), "l"(g) : "memory");
}
#define CP_COMMIT() asm volatile("cp.async.commit_group;" ::: "memory")
#define CP_WAIT(n)  asm volatile("cp.async.wait_group %0;" :: "n"(n) : "memory")

__device__ __forceinline__ void ldm4(uint32_t addr, uint32_t r[4]) {
    asm volatile("ldmatrix.sync.aligned.m8n8.x4.shared.b16 {%0,%1,%2,%3}, [%4];"
                 : "=r"(r[0]), "=r"(r[1]), "=r"(r[2]), "=r"(r[3]) : "r"(addr));
}

__device__ __forceinline__ void ldm4t(uint32_t addr, uint32_t r[4]) {
    asm volatile("ldmatrix.sync.aligned.m8n8.x4.trans.shared.b16 {%0,%1,%2,%3}, [%4];"
                 : "=r"(r[0]), "=r"(r[1]), "=r"(r[2]), "=r"(r[3]) : "r"(addr));
}

__device__ __forceinline__ void mma_hf(float* c, const uint32_t* a, uint32_t b0, uint32_t b1) {
    asm volatile(
        "mma.sync.aligned.m16n8k16.row.col.f32.f16.f16.f32 "
        "{%0,%1,%2,%3}, {%4,%5,%6,%7}, {%8,%9}, {%0,%1,%2,%3};"
        : "+f"(c[0]), "+f"(c[1]), "+f"(c[2]), "+f"(c[3])
        : "r"(a[0]), "r"(a[1]), "r"(a[2]), "r"(a[3]), "r"(b0), "r"(b1));
}

// ---------------- GEMM config ----------------
// CTA tile 128x128, 256 thr = 8 warps (2 M x 4 N), warp tile 64x32.
// K-chunk 64. A/K-major tiles: 128B data + 16B pad per row (ROWP=144).
// PV's V tile (natural [k,n] layout): 64 rows x 256B data + 16B pad (ROWB=272).
#define ROWP     144
#define TILE_B   (128 * ROWP)          // 18432
#define ROWB     272
#define TILE_BB  (64 * ROWB)           // 17408
// K-major pair (proj/scores): 2 tiles per stage
#define OFF3_A   0
#define OFF3_B   (1 * TILE_B)
#define STAGE3_B (2 * TILE_B)          // 36864
#define SMEM_ALLOC3 (2 * STAGE3_B)     // 73728
// pv: A (144B rows) + V (272B rows)
#define OFFP_A   0
#define OFFP_B   TILE_B
#define STAGEP_B (TILE_B + TILE_BB)    // 35840
#define SMEM_ALLOCP (2 * STAGEP_B)     // 71680
#define NTHR     256

// one 128x64-elem (2B) K-major tile -> smem (16B chunks, 8 per row); 256 threads
template <typename T>
__device__ __forceinline__ void fill_tile(uint32_t sb, const T* __restrict__ src,
                                          int ld, int k0, int tid) {
#pragma unroll
    for (int v = 0; v < 4; ++v) {
        int idx = v * NTHR + tid;         // 0..1023
        int row = idx >> 3;               // 0..127
        int c16 = idx & 7;                // 0..7
        cp16(sb + row * ROWP + c16 * 16, src + (size_t)row * ld + k0 + c16 * 8);
    }
}

// one 64(k) x 128(n) fp16 tile from natural [s,d] V layout; rows 256B + pad
__device__ __forceinline__ void fill_vtile(uint32_t sb, const __half* __restrict__ src,
                                           int k0, int tid) {
#pragma unroll
    for (int v = 0; v < 4; ++v) {
        int idx = v * NTHR + tid;         // 0..1023
        int row = idx >> 4;               // 0..63
        int c16 = idx & 15;               // 0..15
        cp16(sb + row * ROWB + c16 * 16, src + (size_t)(k0 + row) * DIM + c16 * 8);
    }
}

// ---------------- plain fp16 mainloop (proj & scores; both operands K-major) --
__device__ __forceinline__ void gemm_fp16(
    const __half* __restrict__ A, int lda,
    const __half* __restrict__ B, int ldb,
    int ktotal, float acc[4][4][4])
{
    extern __shared__ char rawsm[];
    const uint32_t smb = smem_u32(rawsm);
    const int tid  = threadIdx.x;
    const int lane = tid & 31;
    const int wid  = tid >> 5;
    const int wm   = wid >> 2;
    const int wn   = wid & 3;

#pragma unroll
    for (int i = 0; i < 4; ++i)
#pragma unroll
        for (int j = 0; j < 4; ++j)
#pragma unroll
            for (int k = 0; k < 4; ++k) acc[i][j][k] = 0.f;

    const int nch = ktotal >> 6;

    fill_tile(smb + OFF3_A, A, lda, 0, tid);
    fill_tile(smb + OFF3_B, B, ldb, 0, tid);
    CP_COMMIT();

    const uint32_t a_row_off = (uint32_t)((wm * 64 + (lane & 15)) * ROWP);
    const uint32_t b_row_off = (uint32_t)((wn * 32 + (lane & 7) + ((lane >> 3) & 1) * 8) * ROWP);
    const uint32_t k_half    = (uint32_t)(((lane >> 4) & 1) * 16);

    for (int c = 0; c < nch; ++c) {
        CP_WAIT(0);
        __syncthreads();
        if (c + 1 < nch) {
            const uint32_t nb = smb + (uint32_t)(((c + 1) & 1) * STAGE3_B);
            const int nk = (c + 1) << 6;
            fill_tile(nb + OFF3_A, A, lda, nk, tid);
            fill_tile(nb + OFF3_B, B, ldb, nk, tid);
            CP_COMMIT();
        }

        const uint32_t sb = smb + (uint32_t)((c & 1) * STAGE3_B);

#pragma unroll
        for (int ks = 0; ks < 4; ++ks) {
            const uint32_t ko = (uint32_t)(ks * 32) + k_half;

            uint32_t ra[4][4], rb[2][4];
#pragma unroll
            for (int mf = 0; mf < 4; ++mf)
                ldm4(sb + OFF3_A + a_row_off + (uint32_t)(mf * 16 * ROWP) + ko, ra[mf]);
#pragma unroll
            for (int bf = 0; bf < 2; ++bf)
                ldm4(sb + OFF3_B + b_row_off + (uint32_t)(bf * 16 * ROWP) + ko, rb[bf]);

#pragma unroll
            for (int mf = 0; mf < 4; ++mf)
#pragma unroll
                for (int bf = 0; bf < 2; ++bf) {
                    mma_hf(acc[mf][bf * 2],     ra[mf], rb[bf][0], rb[bf][2]);
                    mma_hf(acc[mf][bf * 2 + 1], ra[mf], rb[bf][1], rb[bf][3]);
                }
        }
    }
    __syncthreads();
}

// ---------------- pv mainloop: A K-major (P), B from natural V via ldmatrix.trans
__device__ __forceinline__ void gemm_fp16_pv(
    const __half* __restrict__ A, int lda,
    const __half* __restrict__ V,          // pre-offset: g_Vf + b*SEQ*DIM + nt*128
    int ktotal, float acc[4][4][4])
{
    extern __shared__ char rawsm[];
    const uint32_t smb = smem_u32(rawsm);
    const int tid  = threadIdx.x;
    const int lane = tid & 31;
    const int wid  = tid >> 5;
    const int wm   = wid >> 2;
    const int wn   = wid & 3;

#pragma unroll
    for (int i = 0; i < 4; ++i)
#pragma unroll
        for (int j = 0; j < 4; ++j)
#pragma unroll
            for (int k = 0; k < 4; ++k) acc[i][j][k] = 0.f;

    const int nch = ktotal >> 6;

    fill_tile(smb + OFFP_A, A, lda, 0, tid);
    fill_vtile(smb + OFFP_B, V, 0, tid);
    CP_COMMIT();

    const uint32_t a_row_off = (uint32_t)((wm * 64 + (lane & 15)) * ROWP);
    const uint32_t k_half    = (uint32_t)(((lane >> 4) & 1) * 16);
    // trans B addressing: k_row = (lane&7) + ((lane>>4)&1)*8 ; n byte off = wn*64 + ((lane>>3)&1)*16
    const uint32_t bt_off = (uint32_t)(((lane & 7) + ((lane >> 4) & 1) * 8) * ROWB
                                       + wn * 64 + ((lane >> 3) & 1) * 16);

    for (int c = 0; c < nch; ++c) {
        CP_WAIT(0);
        __syncthreads();
        if (c + 1 < nch) {
            const uint32_t nb = smb + (uint32_t)(((c + 1) & 1) * STAGEP_B);
            const int nk = (c + 1) << 6;
            fill_tile(nb + OFFP_A, A, lda, nk, tid);
            fill_vtile(nb + OFFP_B, V, nk, tid);
            CP_COMMIT();
        }

        const uint32_t sb = smb + (uint32_t)((c & 1) * STAGEP_B);

#pragma unroll
        for (int ks = 0; ks < 4; ++ks) {
            const uint32_t ko = (uint32_t)(ks * 32) + k_half;

            uint32_t ra[4][4], rb[2][4];
#pragma unroll
            for (int mf = 0; mf < 4; ++mf)
                ldm4(sb + OFFP_A + a_row_off + (uint32_t)(mf * 16 * ROWP) + ko, ra[mf]);
#pragma unroll
            for (int bf = 0; bf < 2; ++bf)
                ldm4t(sb + OFFP_B + (uint32_t)(ks * 16 * ROWB) + bt_off + (uint32_t)(bf * 32),
                      rb[bf]);

#pragma unroll
            for (int mf = 0; mf < 4; ++mf)
#pragma unroll
                for (int bf = 0; bf < 2; ++bf) {
                    mma_hf(acc[mf][bf * 2],     ra[mf], rb[bf][0], rb[bf][2]);
                    mma_hf(acc[mf][bf * 2 + 1], ra[mf], rb[bf][1], rb[bf][3]);
                }
        }
    }
    __syncthreads();
}

// ---------------- stage kernels ----------------

// X and W -> plain fp16, one launch
__global__ __launch_bounds__(1024) void convert_kernel(const float* __restrict__ x,
                                                       const float* __restrict__ wq,
                                                       const float* __restrict__ wk,
                                                       const float* __restrict__ wv) {
    size_t i = (size_t)blockIdx.x * blockDim.x + threadIdx.x;
    if (i < NSD) {
        g_Xf[i] = __float2half_rn(x[i]);
    } else if (i < NSD + NW) {
        size_t j = i - NSD;
        size_t which = j >> 18;
        size_t off   = j & 262143ull;
        const float* src = (which == 0) ? wq : (which == 1) ? wk : wv;
        g_Wf[j] = __float2half_rn(src[off]);
    }
}

// QKV projection (plain fp16): grid (4 ntile, 128 mtile, 3 which)
__global__ __launch_bounds__(NTHR) void proj_kernel() {
    const int nt = blockIdx.x, mt = blockIdx.y, z = blockIdx.z;
    const __half* A = g_Xf + (size_t)mt * 128 * DIM;
    const __half* B = g_Wf + (size_t)z * DIM * DIM + (size_t)nt * 128 * DIM;

    float acc[4][4][4];
    gemm_fp16(A, DIM, B, DIM, DIM, acc);

    __half* dst0 = (z == 0) ? g_Qf : (z == 1) ? g_Kf : g_Vf;

    const int lane = threadIdx.x & 31, wid = threadIdx.x >> 5;
    const int wm = wid >> 2, wn = wid & 3;
    const int g = lane >> 2, t = lane & 3;
    const size_t rbase = (size_t)mt * 128;
    const int cbase = nt * 128 + wn * 32 + 2 * t;

#pragma unroll
    for (int mf = 0; mf < 4; ++mf) {
#pragma unroll
        for (int nf = 0; nf < 4; ++nf) {
            const int col = cbase + nf * 8;
#pragma unroll
            for (int half = 0; half < 2; ++half) {
                const int row = wm * 64 + mf * 16 + g + half * 8;
                float v0 = acc[mf][nf][half * 2];
                float v1 = acc[mf][nf][half * 2 + 1];
                size_t o = (rbase + row) * DIM + col;
                *reinterpret_cast<__half2*>(dst0 + o) =
                    __halves2half2(__float2half_rn(v0), __float2half_rn(v1));
            }
        }
    }
}

// Scores (plain fp16): grid (32 kt, 32 qt, 4 b), skip kt > qt
__global__ __launch_bounds__(NTHR) void scores_kernel() {
    const int kt = blockIdx.x, qt = blockIdx.y, b = blockIdx.z;
    if (kt > qt) return;

    const size_t qoff = ((size_t)b * SEQ + (size_t)qt * 128) * DIM;
    const size_t koff = ((size_t)b * SEQ + (size_t)kt * 128) * DIM;

    float acc[4][4][4];
    gemm_fp16(g_Qf + qoff, DIM, g_Kf + koff, DIM, DIM, acc);

    const int lane = threadIdx.x & 31, wid = threadIdx.x >> 5;
    const int wm = wid >> 2, wn = wid & 3;
    const int g = lane >> 2, t = lane & 3;
    const float scale = 0.04419417382415922f;   // 1/sqrt(512)

#pragma unroll
    for (int mf = 0; mf < 4; ++mf) {
#pragma unroll
        for (int nf = 0; nf < 4; ++nf) {
            const int col = kt * 128 + wn * 32 + nf * 8 + 2 * t;
#pragma unroll
            for (int half = 0; half < 2; ++half) {
                const int qrow = qt * 128 + wm * 64 + mf * 16 + g + half * 8;
                float v0 = (col     <= qrow) ? acc[mf][nf][half * 2]     * scale : -1e30f;
                float v1 = (col + 1 <= qrow) ? acc[mf][nf][half * 2 + 1] * scale : -1e30f;
                float* dst = g_P + ((size_t)b * SEQ + qrow) * SEQ + col;
                *reinterpret_cast<float2*>(dst) = make_float2(v0, v1);
            }
        }
    }
}

// Row softmax over [0, jend): one gmem read, row cached in registers.
__global__ __launch_bounds__(256) void softmax_kernel() {
    const int rr = blockIdx.x;
    const int b = rr >> 12;
    const int i = rr & 4095;
    const size_t rowoff = ((size_t)b * SEQ + i) * SEQ;
    const float* row = g_P + rowoff;
    const int jend = ((i >> 7) + 1) << 7;

    const int tid = threadIdx.x, lane = tid & 31, wid = tid >> 5;
    __shared__ float red[8];

    float v[16];
    int cnt = 0;
    float m = -1e30f;
    for (int j = tid; j < jend; j += 256) {
        float x = row[j];
        v[cnt++] = x;
        m = fmaxf(m, x);
    }
#pragma unroll
    for (int o = 16; o > 0; o >>= 1) m = fmaxf(m, __shfl_xor_sync(0xffffffffu, m, o));
    if (lane == 0) red[wid] = m;
    __syncthreads();
    m = red[0];
#pragma unroll
    for (int w = 1; w < 8; w++) m = fmaxf(m, red[w]);

    float s = 0.f;
    for (int k = 0; k < cnt; ++k) {
        float e = __expf(v[k] - m);
        v[k] = e;
        s += e;
    }
#pragma unroll
    for (int o = 16; o > 0; o >>= 1) s += __shfl_xor_sync(0xffffffffu, s, o);
    __syncthreads();
    if (lane == 0) red[wid] = s;
    __syncthreads();
    s = red[0];
#pragma unroll
    for (int w = 1; w < 8; w++) s += red[w];

    const float inv = 1.0f / s;
    cnt = 0;
    for (int j = tid; j < jend; j += 256)
        g_Ph[rowoff + j] = __float2half_rn(v[cnt++] * inv);
}

// PV (plain fp16, V loaded natural-layout via ldmatrix.trans):
// grid (4 ntile, 32 qt, 4 b), K bounded by causal extent
__global__ __launch_bounds__(NTHR) void pv_kernel(float* __restrict__ out) {
    const int nt = blockIdx.x, qt = blockIdx.y, b = blockIdx.z;

    const size_t poff = ((size_t)b * SEQ + (size_t)qt * 128) * SEQ;
    const __half* Vb = g_Vf + (size_t)b * SEQ * DIM + nt * 128;
    const int kmax = (qt + 1) * 128;

    float acc[4][4][4];
    gemm_fp16_pv(g_Ph + poff, SEQ, Vb, kmax, acc);

    const int lane = threadIdx.x & 31, wid = threadIdx.x >> 5;
    const int wm = wid >> 2, wn = wid & 3;
    const int g = lane >> 2, t = lane & 3;

#pragma unroll
    for (int mf = 0; mf < 4; ++mf) {
#pragma unroll
        for (int nf = 0; nf < 4; ++nf) {
            const int col = nt * 128 + wn * 32 + nf * 8 + 2 * t;
#pragma unroll
            for (int half = 0; half < 2; ++half) {
                const int row = qt * 128 + wm * 64 + mf * 16 + g + half * 8;
                float* dst = out + ((size_t)b * SEQ + row) * DIM + col;
                *reinterpret_cast<float2*>(dst) =
                    make_float2(acc[mf][nf][half * 2], acc[mf][nf][half * 2 + 1]);
            }
        }
    }
}

// ---------------- launch ----------------
extern "C" void kernel_launch(void* const* d_in, const int* in_sizes, int n_in,
                              void* d_out, int out_size)
{
    const float* x  = (const float*)d_in[0];
    const float* WQ = (const float*)d_in[1];
    const float* WK = (const float*)d_in[2];
    const float* WV = (const float*)d_in[3];
    float* out = (float*)d_out;

    cudaFuncSetAttribute(proj_kernel,   cudaFuncAttributeMaxDynamicSharedMemorySize, SMEM_ALLOC3);
    cudaFuncSetAttribute(scores_kernel, cudaFuncAttributeMaxDynamicSharedMemorySize, SMEM_ALLOC3);
    cudaFuncSetAttribute(pv_kernel,     cudaFuncAttributeMaxDynamicSharedMemorySize, SMEM_ALLOCP);

    convert_kernel<<<8960, 1024>>>(x, WQ, WK, WV);   // covers NSD + NW

    proj_kernel<<<dim3(4, 128, 3), NTHR, SMEM_ALLOC3>>>();

    scores_kernel<<<dim3(32, 32, 4), NTHR, SMEM_ALLOC3>>>();

    softmax_kernel<<<BATCH * SEQ, 256>>>();

    pv_kernel<<<dim3(4, 32, 4), NTHR, SMEM_ALLOCP>>>(out);
}

// round 12
// speedup vs baseline: 4.2027x; 1.0867x over previous
#include <cuda_runtime.h>
#include <cuda_fp16.h>
#include <cstdint>

#define BATCH 4
#define SEQ   4096
#define DIM   512

#define NSD (4ull*4096ull*512ull)     // 8,388,608
#define NW  (3ull*512ull*512ull)      // 786,432
#define NSS (4ull*4096ull*4096ull)    // 67,108,864

// ---------------- static scratch (allocation-free) ----------------
__device__ __half g_Xf[NSD];                 // X plain fp16
__device__ __half g_Wf[NW];                  // weights plain fp16
__device__ __half g_Qf[NSD];
__device__ __half g_Kf[NSD];
__device__ __half g_Vf[NSD];
__device__ float  g_P[NSS];
__device__ __half g_Ph[NSS];

// ---------------- PTX helpers (compute_103-baseline ISA only) ----------------
__device__ __forceinline__ uint32_t smem_u32(const void* p) {
    uint32_t a;
    asm("{ .reg .u64 t; cvta.to.shared.u64 t, %1; cvt.u32.u64 %0, t; }" : "=r"(a) : "l"(p));
    return a;
}

__device__ __forceinline__ void cp16(uint32_t s, const void* g) {
    asm volatile("cp.async.cg.shared.global [%0], [%1], 16;" :: "r"(s), "l"(g) : "memory");
}
#define CP_COMMIT() asm volatile("cp.async.commit_group;" ::: "memory")
#define CP_WAIT(n)  asm volatile("cp.async.wait_group %0;" :: "n"(n) : "memory")

__device__ __forceinline__ void ldm4(uint32_t addr, uint32_t r[4]) {
    asm volatile("ldmatrix.sync.aligned.m8n8.x4.shared.b16 {%0,%1,%2,%3}, [%4];"
                 : "=r"(r[0]), "=r"(r[1]), "=r"(r[2]), "=r"(r[3]) : "r"(addr));
}

__device__ __forceinline__ void ldm4t(uint32_t addr, uint32_t r[4]) {
    asm volatile("ldmatrix.sync.aligned.m8n8.x4.trans.shared.b16 {%0,%1,%2,%3}, [%4];"
                 : "=r"(r[0]), "=r"(r[1]), "=r"(r[2]), "=r"(r[3]) : "r"(addr));
}

__device__ __forceinline__ void mma_hf(float* c, const uint32_t* a, uint32_t b0, uint32_t b1) {
    asm volatile(
        "mma.sync.aligned.m16n8k16.row.col.f32.f16.f16.f32 "
        "{%0,%1,%2,%3}, {%4,%5,%6,%7}, {%8,%9}, {%0,%1,%2,%3};"
        : "+f"(c[0]), "+f"(c[1]), "+f"(c[2]), "+f"(c[3])
        : "r"(a[0]), "r"(a[1]), "r"(a[2]), "r"(a[3]), "r"(b0), "r"(b1));
}

// ---------------- GEMM config ----------------
#define ROWP     144
#define TILE_B   (128 * ROWP)          // 18432
#define ROWB     272
#define TILE_BB  (64 * ROWB)           // 17408
#define OFF3_A   0
#define OFF3_B   (1 * TILE_B)
#define STAGE3_B (2 * TILE_B)          // 36864
#define SMEM_ALLOC3 (2 * STAGE3_B)     // 73728
#define OFFP_A   0
#define OFFP_B   TILE_B
#define STAGEP_B (TILE_B + TILE_BB)    // 35840
#define SMEM_ALLOCP (2 * STAGEP_B)     // 71680
#define NTHR     256

template <typename T>
__device__ __forceinline__ void fill_tile(uint32_t sb, const T* __restrict__ src,
                                          int ld, int k0, int tid) {
#pragma unroll
    for (int v = 0; v < 4; ++v) {
        int idx = v * NTHR + tid;
        int row = idx >> 3;
        int c16 = idx & 7;
        cp16(sb + row * ROWP + c16 * 16, src + (size_t)row * ld + k0 + c16 * 8);
    }
}

__device__ __forceinline__ void fill_vtile(uint32_t sb, const __half* __restrict__ src,
                                           int k0, int tid) {
#pragma unroll
    for (int v = 0; v < 4; ++v) {
        int idx = v * NTHR + tid;
        int row = idx >> 4;
        int c16 = idx & 15;
        cp16(sb + row * ROWB + c16 * 16, src + (size_t)(k0 + row) * DIM + c16 * 8);
    }
}

// ---------------- plain fp16 mainloop (proj & scores) ----------------
__device__ __forceinline__ void gemm_fp16(
    const __half* __restrict__ A, int lda,
    const __half* __restrict__ B, int ldb,
    int ktotal, float acc[4][4][4])
{
    extern __shared__ char rawsm[];
    const uint32_t smb = smem_u32(rawsm);
    const int tid  = threadIdx.x;
    const int lane = tid & 31;
    const int wid  = tid >> 5;
    const int wm   = wid >> 2;
    const int wn   = wid & 3;

#pragma unroll
    for (int i = 0; i < 4; ++i)
#pragma unroll
        for (int j = 0; j < 4; ++j)
#pragma unroll
            for (int k = 0; k < 4; ++k) acc[i][j][k] = 0.f;

    const int nch = ktotal >> 6;

    fill_tile(smb + OFF3_A, A, lda, 0, tid);
    fill_tile(smb + OFF3_B, B, ldb, 0, tid);
    CP_COMMIT();

    const uint32_t a_row_off = (uint32_t)((wm * 64 + (lane & 15)) * ROWP);
    const uint32_t b_row_off = (uint32_t)((wn * 32 + (lane & 7) + ((lane >> 3) & 1) * 8) * ROWP);
    const uint32_t k_half    = (uint32_t)(((lane >> 4) & 1) * 16);

    for (int c = 0; c < nch; ++c) {
        CP_WAIT(0);
        __syncthreads();
        if (c + 1 < nch) {
            const uint32_t nb = smb + (uint32_t)(((c + 1) & 1) * STAGE3_B);
            const int nk = (c + 1) << 6;
            fill_tile(nb + OFF3_A, A, lda, nk, tid);
            fill_tile(nb + OFF3_B, B, ldb, nk, tid);
            CP_COMMIT();
        }

        const uint32_t sb = smb + (uint32_t)((c & 1) * STAGE3_B);

#pragma unroll
        for (int ks = 0; ks < 4; ++ks) {
            const uint32_t ko = (uint32_t)(ks * 32) + k_half;

            uint32_t ra[4][4], rb[2][4];
#pragma unroll
            for (int mf = 0; mf < 4; ++mf)
                ldm4(sb + OFF3_A + a_row_off + (uint32_t)(mf * 16 * ROWP) + ko, ra[mf]);
#pragma unroll
            for (int bf = 0; bf < 2; ++bf)
                ldm4(sb + OFF3_B + b_row_off + (uint32_t)(bf * 16 * ROWP) + ko, rb[bf]);

#pragma unroll
            for (int mf = 0; mf < 4; ++mf)
#pragma unroll
                for (int bf = 0; bf < 2; ++bf) {
                    mma_hf(acc[mf][bf * 2],     ra[mf], rb[bf][0], rb[bf][2]);
                    mma_hf(acc[mf][bf * 2 + 1], ra[mf], rb[bf][1], rb[bf][3]);
                }
        }
    }
    __syncthreads();
}

// ---------------- pv mainloop: B from natural V via ldmatrix.trans ----------
__device__ __forceinline__ void gemm_fp16_pv(
    const __half* __restrict__ A, int lda,
    const __half* __restrict__ V,
    int ktotal, float acc[4][4][4])
{
    extern __shared__ char rawsm[];
    const uint32_t smb = smem_u32(rawsm);
    const int tid  = threadIdx.x;
    const int lane = tid & 31;
    const int wid  = tid >> 5;
    const int wm   = wid >> 2;
    const int wn   = wid & 3;

#pragma unroll
    for (int i = 0; i < 4; ++i)
#pragma unroll
        for (int j = 0; j < 4; ++j)
#pragma unroll
            for (int k = 0; k < 4; ++k) acc[i][j][k] = 0.f;

    const int nch = ktotal >> 6;

    fill_tile(smb + OFFP_A, A, lda, 0, tid);
    fill_vtile(smb + OFFP_B, V, 0, tid);
    CP_COMMIT();

    const uint32_t a_row_off = (uint32_t)((wm * 64 + (lane & 15)) * ROWP);
    const uint32_t k_half    = (uint32_t)(((lane >> 4) & 1) * 16);
    const uint32_t bt_off = (uint32_t)(((lane & 7) + ((lane >> 4) & 1) * 8) * ROWB
                                       + wn * 64 + ((lane >> 3) & 1) * 16);

    for (int c = 0; c < nch; ++c) {
        CP_WAIT(0);
        __syncthreads();
        if (c + 1 < nch) {
            const uint32_t nb = smb + (uint32_t)(((c + 1) & 1) * STAGEP_B);
            const int nk = (c + 1) << 6;
            fill_tile(nb + OFFP_A, A, lda, nk, tid);
            fill_vtile(nb + OFFP_B, V, nk, tid);
            CP_COMMIT();
        }

        const uint32_t sb = smb + (uint32_t)((c & 1) * STAGEP_B);

#pragma unroll
        for (int ks = 0; ks < 4; ++ks) {
            const uint32_t ko = (uint32_t)(ks * 32) + k_half;

            uint32_t ra[4][4], rb[2][4];
#pragma unroll
            for (int mf = 0; mf < 4; ++mf)
                ldm4(sb + OFFP_A + a_row_off + (uint32_t)(mf * 16 * ROWP) + ko, ra[mf]);
#pragma unroll
            for (int bf = 0; bf < 2; ++bf)
                ldm4t(sb + OFFP_B + (uint32_t)(ks * 16 * ROWB) + bt_off + (uint32_t)(bf * 32),
                      rb[bf]);

#pragma unroll
            for (int mf = 0; mf < 4; ++mf)
#pragma unroll
                for (int bf = 0; bf < 2; ++bf) {
                    mma_hf(acc[mf][bf * 2],     ra[mf], rb[bf][0], rb[bf][2]);
                    mma_hf(acc[mf][bf * 2 + 1], ra[mf], rb[bf][1], rb[bf][3]);
                }
        }
    }
    __syncthreads();
}

// ---------------- stage kernels ----------------

// X and W -> plain fp16, vectorized 4-wide, one launch
__global__ __launch_bounds__(1024) void convert_kernel(const float* __restrict__ x,
                                                       const float* __restrict__ wq,
                                                       const float* __restrict__ wk,
                                                       const float* __restrict__ wv) {
    size_t i = (size_t)blockIdx.x * blockDim.x + threadIdx.x;   // float4 index
    const size_t nx4 = NSD >> 2, nw4 = NW >> 2, nwq4 = (NW / 3) >> 2;
    if (i < nx4) {
        float4 v = reinterpret_cast<const float4*>(x)[i];
        __half2 h0 = __halves2half2(__float2half_rn(v.x), __float2half_rn(v.y));
        __half2 h1 = __halves2half2(__float2half_rn(v.z), __float2half_rn(v.w));
        reinterpret_cast<__half2*>(g_Xf)[i * 2]     = h0;
        reinterpret_cast<__half2*>(g_Xf)[i * 2 + 1] = h1;
    } else if (i < nx4 + nw4) {
        size_t j = i - nx4;
        size_t which = j / nwq4;
        size_t off   = j - which * nwq4;
        const float* src = (which == 0) ? wq : (which == 1) ? wk : wv;
        float4 v = reinterpret_cast<const float4*>(src)[off];
        __half2 h0 = __halves2half2(__float2half_rn(v.x), __float2half_rn(v.y));
        __half2 h1 = __halves2half2(__float2half_rn(v.z), __float2half_rn(v.w));
        reinterpret_cast<__half2*>(g_Wf)[j * 2]     = h0;
        reinterpret_cast<__half2*>(g_Wf)[j * 2 + 1] = h1;
    }
}

// QKV projection: grid (4 ntile, 128 mtile, 3 which)
__global__ __launch_bounds__(NTHR) void proj_kernel() {
    const int nt = blockIdx.x, mt = blockIdx.y, z = blockIdx.z;
    const __half* A = g_Xf + (size_t)mt * 128 * DIM;
    const __half* B = g_Wf + (size_t)z * DIM * DIM + (size_t)nt * 128 * DIM;

    float acc[4][4][4];
    gemm_fp16(A, DIM, B, DIM, DIM, acc);

    __half* dst0 = (z == 0) ? g_Qf : (z == 1) ? g_Kf : g_Vf;

    const int lane = threadIdx.x & 31, wid = threadIdx.x >> 5;
    const int wm = wid >> 2, wn = wid & 3;
    const int g = lane >> 2, t = lane & 3;
    const size_t rbase = (size_t)mt * 128;
    const int cbase = nt * 128 + wn * 32 + 2 * t;

#pragma unroll
    for (int mf = 0; mf < 4; ++mf) {
#pragma unroll
        for (int nf = 0; nf < 4; ++nf) {
            const int col = cbase + nf * 8;
#pragma unroll
            for (int half = 0; half < 2; ++half) {
                const int row = wm * 64 + mf * 16 + g + half * 8;
                float v0 = acc[mf][nf][half * 2];
                float v1 = acc[mf][nf][half * 2 + 1];
                size_t o = (rbase + row) * DIM + col;
                *reinterpret_cast<__half2*>(dst0 + o) =
                    __halves2half2(__float2half_rn(v0), __float2half_rn(v1));
            }
        }
    }
}

// Scores: grid (32 kt, 32 qt, 4 b), skip kt > qt
__global__ __launch_bounds__(NTHR) void scores_kernel() {
    const int kt = blockIdx.x, qt = blockIdx.y, b = blockIdx.z;
    if (kt > qt) return;

    const size_t qoff = ((size_t)b * SEQ + (size_t)qt * 128) * DIM;
    const size_t koff = ((size_t)b * SEQ + (size_t)kt * 128) * DIM;

    float acc[4][4][4];
    gemm_fp16(g_Qf + qoff, DIM, g_Kf + koff, DIM, DIM, acc);

    const int lane = threadIdx.x & 31, wid = threadIdx.x >> 5;
    const int wm = wid >> 2, wn = wid & 3;
    const int g = lane >> 2, t = lane & 3;
    const float scale = 0.04419417382415922f;   // 1/sqrt(512)

#pragma unroll
    for (int mf = 0; mf < 4; ++mf) {
#pragma unroll
        for (int nf = 0; nf < 4; ++nf) {
            const int col = kt * 128 + wn * 32 + nf * 8 + 2 * t;
#pragma unroll
            for (int half = 0; half < 2; ++half) {
                const int qrow = qt * 128 + wm * 64 + mf * 16 + g + half * 8;
                float v0 = (col     <= qrow) ? acc[mf][nf][half * 2]     * scale : -1e30f;
                float v1 = (col + 1 <= qrow) ? acc[mf][nf][half * 2 + 1] * scale : -1e30f;
                float* dst = g_P + ((size_t)b * SEQ + qrow) * SEQ + col;
                *reinterpret_cast<float2*>(dst) = make_float2(v0, v1);
            }
        }
    }
}

// Row softmax over [0, jend): vectorized 4-wide, one gmem read, register cache.
__global__ __launch_bounds__(256) void softmax_kernel() {
    const int rr = blockIdx.x;
    const int b = rr >> 12;
    const int i = rr & 4095;
    const size_t rowoff = ((size_t)b * SEQ + i) * SEQ;
    const float4* row4 = reinterpret_cast<const float4*>(g_P + rowoff);
    const int jend4 = (((i >> 7) + 1) << 7) >> 2;    // multiple of 32

    const int tid = threadIdx.x, lane = tid & 31, wid = tid >> 5;
    __shared__ float red[8];

    float4 v[4];
    int cnt = 0;
    float m = -1e30f;
    for (int j = tid; j < jend4; j += 256) {
        float4 x = row4[j];
        v[cnt++] = x;
        m = fmaxf(m, fmaxf(fmaxf(x.x, x.y), fmaxf(x.z, x.w)));
    }
#pragma unroll
    for (int o = 16; o > 0; o >>= 1) m = fmaxf(m, __shfl_xor_sync(0xffffffffu, m, o));
    if (lane == 0) red[wid] = m;
    __syncthreads();
    m = red[0];
#pragma unroll
    for (int w = 1; w < 8; w++) m = fmaxf(m, red[w]);

    float s = 0.f;
    for (int k = 0; k < cnt; ++k) {
        float4 e;
        e.x = __expf(v[k].x - m);
        e.y = __expf(v[k].y - m);
        e.z = __expf(v[k].z - m);
        e.w = __expf(v[k].w - m);
        v[k] = e;
        s += (e.x + e.y) + (e.z + e.w);
    }
#pragma unroll
    for (int o = 16; o > 0; o >>= 1) s += __shfl_xor_sync(0xffffffffu, s, o);
    __syncthreads();
    if (lane == 0) red[wid] = s;
    __syncthreads();
    s = red[0];
#pragma unroll
    for (int w = 1; w < 8; w++) s += red[w];

    const float inv = 1.0f / s;
    uint2* out4 = reinterpret_cast<uint2*>(g_Ph + rowoff);   // 4 halves per uint2
    cnt = 0;
    for (int j = tid; j < jend4; j += 256) {
        float4 e = v[cnt++];
        __half2 h0 = __halves2half2(__float2half_rn(e.x * inv), __float2half_rn(e.y * inv));
        __half2 h1 = __halves2half2(__float2half_rn(e.z * inv), __float2half_rn(e.w * inv));
        uint2 pk;
        pk.x = *reinterpret_cast<uint32_t*>(&h0);
        pk.y = *reinterpret_cast<uint32_t*>(&h1);
        out4[j] = pk;
    }
}

// PV: grid (4 ntile, 32 qt, 4 b), K bounded by causal extent
__global__ __launch_bounds__(NTHR) void pv_kernel(float* __restrict__ out) {
    const int nt = blockIdx.x, qt = blockIdx.y, b = blockIdx.z;

    const size_t poff = ((size_t)b * SEQ + (size_t)qt * 128) * SEQ;
    const __half* Vb = g_Vf + (size_t)b * SEQ * DIM + nt * 128;
    const int kmax = (qt + 1) * 128;

    float acc[4][4][4];
    gemm_fp16_pv(g_Ph + poff, SEQ, Vb, kmax, acc);

    const int lane = threadIdx.x & 31, wid = threadIdx.x >> 5;
    const int wm = wid >> 2, wn = wid & 3;
    const int g = lane >> 2, t = lane & 3;

#pragma unroll
    for (int mf = 0; mf < 4; ++mf) {
#pragma unroll
        for (int nf = 0; nf < 4; ++nf) {
            const int col = nt * 128 + wn * 32 + nf * 8 + 2 * t;
#pragma unroll
            for (int half = 0; half < 2; ++half) {
                const int row = qt * 128 + wm * 64 + mf * 16 + g + half * 8;
                float* dst = out + ((size_t)b * SEQ + row) * DIM + col;
                *reinterpret_cast<float2*>(dst) =
                    make_float2(acc[mf][nf][half * 2], acc[mf][nf][half * 2 + 1]);
            }
        }
    }
}

// ---------------- launch ----------------
extern "C" void kernel_launch(void* const* d_in, const int* in_sizes, int n_in,
                              void* d_out, int out_size)
{
    const float* x  = (const float*)d_in[0];
    const float* WQ = (const float*)d_in[1];
    const float* WK = (const float*)d_in[2];
    const float* WV = (const float*)d_in[3];
    float* out = (float*)d_out;

    cudaFuncSetAttribute(proj_kernel,   cudaFuncAttributeMaxDynamicSharedMemorySize, SMEM_ALLOC3);
    cudaFuncSetAttribute(scores_kernel, cudaFuncAttributeMaxDynamicSharedMemorySize, SMEM_ALLOC3);
    cudaFuncSetAttribute(pv_kernel,     cudaFuncAttributeMaxDynamicSharedMemorySize, SMEM_ALLOCP);

    // (NSD + NW) / 4 float4 elements = 2,293,760 -> 2240 blocks of 1024
    convert_kernel<<<2240, 1024>>>(x, WQ, WK, WV);

    proj_kernel<<<dim3(4, 128, 3), NTHR, SMEM_ALLOC3>>>();

    scores_kernel<<<dim3(32, 32, 4), NTHR, SMEM_ALLOC3>>>();

    softmax_kernel<<<BATCH * SEQ, 256>>>();

    pv_kernel<<<dim3(4, 32, 4), NTHR, SMEM_ALLOCP>>>(out);
}

// round 13
// speedup vs baseline: 4.3425x; 1.0333x over previous
#include <cuda_runtime.h>
#include <cuda_fp16.h>
#include <cstdint>

#define BATCH 4
#define SEQ   4096
#define DIM   512

#define NSD (4ull*4096ull*512ull)     // 8,388,608
#define NW  (3ull*512ull*512ull)      // 786,432
#define NSS (4ull*4096ull*4096ull)    // 67,108,864

// ---------------- static scratch (allocation-free) ----------------
__device__ __half g_Xf[NSD];                 // X plain fp16
__device__ __half g_Wf[NW];                  // weights plain fp16
__device__ __half g_Qf[NSD];
__device__ __half g_Kf[NSD];
__device__ __half g_Vf[NSD];
__device__ __half g_Ph[NSS];                 // unnormalized exp(scores), fp16
__device__ float  g_Lpart[(size_t)BATCH * 32 * 128 * 32];  // [b][qt][row][kt], 2 MB

// ---------------- PTX helpers (compute_103-baseline ISA only) ----------------
__device__ __forceinline__ uint32_t smem_u32(const void* p) {
    uint32_t a;
    asm("{ .reg .u64 t; cvta.to.shared.u64 t, %1; cvt.u32.u64 %0, t; }" : "=r"(a) : "l"(p));
    return a;
}

__device__ __forceinline__ void cp16(uint32_t s, const void* g) {
    asm volatile("cp.async.cg.shared.global [%0], [%1], 16;" :: "r"(s), "l"(g) : "memory");
}
#define CP_COMMIT() asm volatile("cp.async.commit_group;" ::: "memory")
#define CP_WAIT(n)  asm volatile("cp.async.wait_group %0;" :: "n"(n) : "memory")

__device__ __forceinline__ void ldm4(uint32_t addr, uint32_t r[4]) {
    asm volatile("ldmatrix.sync.aligned.m8n8.x4.shared.b16 {%0,%1,%2,%3}, [%4];"
                 : "=r"(r[0]), "=r"(r[1]), "=r"(r[2]), "=r"(r[3]) : "r"(addr));
}

__device__ __forceinline__ void ldm4t(uint32_t addr, uint32_t r[4]) {
    asm volatile("ldmatrix.sync.aligned.m8n8.x4.trans.shared.b16 {%0,%1,%2,%3}, [%4];"
                 : "=r"(r[0]), "=r"(r[1]), "=r"(r[2]), "=r"(r[3]) : "r"(addr));
}

__device__ __forceinline__ void mma_hf(float* c, const uint32_t* a, uint32_t b0, uint32_t b1) {
    asm volatile(
        "mma.sync.aligned.m16n8k16.row.col.f32.f16.f16.f32 "
        "{%0,%1,%2,%3}, {%4,%5,%6,%7}, {%8,%9}, {%0,%1,%2,%3};"
        : "+f"(c[0]), "+f"(c[1]), "+f"(c[2]), "+f"(c[3])
        : "r"(a[0]), "r"(a[1]), "r"(a[2]), "r"(a[3]), "r"(b0), "r"(b1));
}

// ---------------- GEMM config ----------------
#define ROWP     144
#define TILE_B   (128 * ROWP)          // 18432
#define ROWB     272
#define TILE_BB  (64 * ROWB)           // 17408
#define OFF3_A   0
#define OFF3_B   (1 * TILE_B)
#define STAGE3_B (2 * TILE_B)          // 36864
#define SMEM_ALLOC3 (2 * STAGE3_B)     // 73728
#define OFFP_A   0
#define OFFP_B   TILE_B
#define STAGEP_B (TILE_B + TILE_BB)    // 35840
#define SMEM_ALLOCP (2 * STAGEP_B)     // 71680
#define NTHR     256

template <typename T>
__device__ __forceinline__ void fill_tile(uint32_t sb, const T* __restrict__ src,
                                          int ld, int k0, int tid) {
#pragma unroll
    for (int v = 0; v < 4; ++v) {
        int idx = v * NTHR + tid;
        int row = idx >> 3;
        int c16 = idx & 7;
        cp16(sb + row * ROWP + c16 * 16, src + (size_t)row * ld + k0 + c16 * 8);
    }
}

__device__ __forceinline__ void fill_vtile(uint32_t sb, const __half* __restrict__ src,
                                           int k0, int tid) {
#pragma unroll
    for (int v = 0; v < 4; ++v) {
        int idx = v * NTHR + tid;
        int row = idx >> 4;
        int c16 = idx & 15;
        cp16(sb + row * ROWB + c16 * 16, src + (size_t)(k0 + row) * DIM + c16 * 8);
    }
}

// ---------------- plain fp16 mainloop (proj & scores) ----------------
__device__ __forceinline__ void gemm_fp16(
    const __half* __restrict__ A, int lda,
    const __half* __restrict__ B, int ldb,
    int ktotal, float acc[4][4][4])
{
    extern __shared__ char rawsm[];
    const uint32_t smb = smem_u32(rawsm);
    const int tid  = threadIdx.x;
    const int lane = tid & 31;
    const int wid  = tid >> 5;
    const int wm   = wid >> 2;
    const int wn   = wid & 3;

#pragma unroll
    for (int i = 0; i < 4; ++i)
#pragma unroll
        for (int j = 0; j < 4; ++j)
#pragma unroll
            for (int k = 0; k < 4; ++k) acc[i][j][k] = 0.f;

    const int nch = ktotal >> 6;

    fill_tile(smb + OFF3_A, A, lda, 0, tid);
    fill_tile(smb + OFF3_B, B, ldb, 0, tid);
    CP_COMMIT();

    const uint32_t a_row_off = (uint32_t)((wm * 64 + (lane & 15)) * ROWP);
    const uint32_t b_row_off = (uint32_t)((wn * 32 + (lane & 7) + ((lane >> 3) & 1) * 8) * ROWP);
    const uint32_t k_half    = (uint32_t)(((lane >> 4) & 1) * 16);

    for (int c = 0; c < nch; ++c) {
        CP_WAIT(0);
        __syncthreads();
        if (c + 1 < nch) {
            const uint32_t nb = smb + (uint32_t)(((c + 1) & 1) * STAGE3_B);
            const int nk = (c + 1) << 6;
            fill_tile(nb + OFF3_A, A, lda, nk, tid);
            fill_tile(nb + OFF3_B, B, ldb, nk, tid);
            CP_COMMIT();
        }

        const uint32_t sb = smb + (uint32_t)((c & 1) * STAGE3_B);

#pragma unroll
        for (int ks = 0; ks < 4; ++ks) {
            const uint32_t ko = (uint32_t)(ks * 32) + k_half;

            uint32_t ra[4][4], rb[2][4];
#pragma unroll
            for (int mf = 0; mf < 4; ++mf)
                ldm4(sb + OFF3_A + a_row_off + (uint32_t)(mf * 16 * ROWP) + ko, ra[mf]);
#pragma unroll
            for (int bf = 0; bf < 2; ++bf)
                ldm4(sb + OFF3_B + b_row_off + (uint32_t)(bf * 16 * ROWP) + ko, rb[bf]);

#pragma unroll
            for (int mf = 0; mf < 4; ++mf)
#pragma unroll
                for (int bf = 0; bf < 2; ++bf) {
                    mma_hf(acc[mf][bf * 2],     ra[mf], rb[bf][0], rb[bf][2]);
                    mma_hf(acc[mf][bf * 2 + 1], ra[mf], rb[bf][1], rb[bf][3]);
                }
        }
    }
    __syncthreads();
}

// ---------------- pv mainloop: B from natural V via ldmatrix.trans ----------
__device__ __forceinline__ void gemm_fp16_pv(
    const __half* __restrict__ A, int lda,
    const __half* __restrict__ V,
    int ktotal, float acc[4][4][4])
{
    extern __shared__ char rawsm[];
    const uint32_t smb = smem_u32(rawsm);
    const int tid  = threadIdx.x;
    const int lane = tid & 31;
    const int wid  = tid >> 5;
    const int wm   = wid >> 2;
    const int wn   = wid & 3;

#pragma unroll
    for (int i = 0; i < 4; ++i)
#pragma unroll
        for (int j = 0; j < 4; ++j)
#pragma unroll
            for (int k = 0; k < 4; ++k) acc[i][j][k] = 0.f;

    const int nch = ktotal >> 6;

    fill_tile(smb + OFFP_A, A, lda, 0, tid);
    fill_vtile(smb + OFFP_B, V, 0, tid);
    CP_COMMIT();

    const uint32_t a_row_off = (uint32_t)((wm * 64 + (lane & 15)) * ROWP);
    const uint32_t k_half    = (uint32_t)(((lane >> 4) & 1) * 16);
    const uint32_t bt_off = (uint32_t)(((lane & 7) + ((lane >> 4) & 1) * 8) * ROWB
                                       + wn * 64 + ((lane >> 3) & 1) * 16);

    for (int c = 0; c < nch; ++c) {
        CP_WAIT(0);
        __syncthreads();
        if (c + 1 < nch) {
            const uint32_t nb = smb + (uint32_t)(((c + 1) & 1) * STAGEP_B);
            const int nk = (c + 1) << 6;
            fill_tile(nb + OFFP_A, A, lda, nk, tid);
            fill_vtile(nb + OFFP_B, V, nk, tid);
            CP_COMMIT();
        }

        const uint32_t sb = smb + (uint32_t)((c & 1) * STAGEP_B);

#pragma unroll
        for (int ks = 0; ks < 4; ++ks) {
            const uint32_t ko = (uint32_t)(ks * 32) + k_half;

            uint32_t ra[4][4], rb[2][4];
#pragma unroll
            for (int mf = 0; mf < 4; ++mf)
                ldm4(sb + OFFP_A + a_row_off + (uint32_t)(mf * 16 * ROWP) + ko, ra[mf]);
#pragma unroll
            for (int bf = 0; bf < 2; ++bf)
                ldm4t(sb + OFFP_B + (uint32_t)(ks * 16 * ROWB) + bt_off + (uint32_t)(bf * 32),
                      rb[bf]);

#pragma unroll
            for (int mf = 0; mf < 4; ++mf)
#pragma unroll
                for (int bf = 0; bf < 2; ++bf) {
                    mma_hf(acc[mf][bf * 2],     ra[mf], rb[bf][0], rb[bf][2]);
                    mma_hf(acc[mf][bf * 2 + 1], ra[mf], rb[bf][1], rb[bf][3]);
                }
        }
    }
    __syncthreads();
}

// ---------------- stage kernels ----------------

// X and W -> plain fp16, vectorized 4-wide, one launch
__global__ __launch_bounds__(1024) void convert_kernel(const float* __restrict__ x,
                                                       const float* __restrict__ wq,
                                                       const float* __restrict__ wk,
                                                       const float* __restrict__ wv) {
    size_t i = (size_t)blockIdx.x * blockDim.x + threadIdx.x;   // float4 index
    const size_t nx4 = NSD >> 2, nw4 = NW >> 2, nwq4 = (NW / 3) >> 2;
    if (i < nx4) {
        float4 v = reinterpret_cast<const float4*>(x)[i];
        __half2 h0 = __halves2half2(__float2half_rn(v.x), __float2half_rn(v.y));
        __half2 h1 = __halves2half2(__float2half_rn(v.z), __float2half_rn(v.w));
        reinterpret_cast<__half2*>(g_Xf)[i * 2]     = h0;
        reinterpret_cast<__half2*>(g_Xf)[i * 2 + 1] = h1;
    } else if (i < nx4 + nw4) {
        size_t j = i - nx4;
        size_t which = j / nwq4;
        size_t off   = j - which * nwq4;
        const float* src = (which == 0) ? wq : (which == 1) ? wk : wv;
        float4 v = reinterpret_cast<const float4*>(src)[off];
        __half2 h0 = __halves2half2(__float2half_rn(v.x), __float2half_rn(v.y));
        __half2 h1 = __halves2half2(__float2half_rn(v.z), __float2half_rn(v.w));
        reinterpret_cast<__half2*>(g_Wf)[j * 2]     = h0;
        reinterpret_cast<__half2*>(g_Wf)[j * 2 + 1] = h1;
    }
}

// QKV projection: grid (4 ntile, 128 mtile, 3 which)
__global__ __launch_bounds__(NTHR) void proj_kernel() {
    const int nt = blockIdx.x, mt = blockIdx.y, z = blockIdx.z;
    const __half* A = g_Xf + (size_t)mt * 128 * DIM;
    const __half* B = g_Wf + (size_t)z * DIM * DIM + (size_t)nt * 128 * DIM;

    float acc[4][4][4];
    gemm_fp16(A, DIM, B, DIM, DIM, acc);

    __half* dst0 = (z == 0) ? g_Qf : (z == 1) ? g_Kf : g_Vf;

    const int lane = threadIdx.x & 31, wid = threadIdx.x >> 5;
    const int wm = wid >> 2, wn = wid & 3;
    const int g = lane >> 2, t = lane & 3;
    const size_t rbase = (size_t)mt * 128;
    const int cbase = nt * 128 + wn * 32 + 2 * t;

#pragma unroll
    for (int mf = 0; mf < 4; ++mf) {
#pragma unroll
        for (int nf = 0; nf < 4; ++nf) {
            const int col = cbase + nf * 8;
#pragma unroll
            for (int half = 0; half < 2; ++half) {
                const int row = wm * 64 + mf * 16 + g + half * 8;
                float v0 = acc[mf][nf][half * 2];
                float v1 = acc[mf][nf][half * 2 + 1];
                size_t o = (rbase + row) * DIM + col;
                *reinterpret_cast<__half2*>(dst0 + o) =
                    __halves2half2(__float2half_rn(v0), __float2half_rn(v1));
            }
        }
    }
}

// Scores + exp + per-tile row sums: grid (32 kt, 32 qt, 4 b), skip kt > qt.
// Writes unnormalized exp(s) in fp16 to g_Ph and per-(row, kt) sums to g_Lpart.
__global__ __launch_bounds__(NTHR) void scores_kernel() {
    const int kt = blockIdx.x, qt = blockIdx.y, b = blockIdx.z;
    if (kt > qt) return;

    const size_t qoff = ((size_t)b * SEQ + (size_t)qt * 128) * DIM;
    const size_t koff = ((size_t)b * SEQ + (size_t)kt * 128) * DIM;

    float acc[4][4][4];
    gemm_fp16(g_Qf + qoff, DIM, g_Kf + koff, DIM, DIM, acc);

    const int lane = threadIdx.x & 31, wid = threadIdx.x >> 5;
    const int wm = wid >> 2, wn = wid & 3;
    const int g = lane >> 2, t = lane & 3;
    const float scale = 0.04419417382415922f;   // 1/sqrt(512)

    float rowpart[4][2];   // per (mf, half): sum of this thread's 8 exp values
#pragma unroll
    for (int mf = 0; mf < 4; ++mf) { rowpart[mf][0] = 0.f; rowpart[mf][1] = 0.f; }

#pragma unroll
    for (int mf = 0; mf < 4; ++mf) {
#pragma unroll
        for (int nf = 0; nf < 4; ++nf) {
            const int col = kt * 128 + wn * 32 + nf * 8 + 2 * t;
#pragma unroll
            for (int half = 0; half < 2; ++half) {
                const int lrow = wm * 64 + mf * 16 + g + half * 8;
                const int qrow = qt * 128 + lrow;
                float e0 = (col     <= qrow) ? __expf(acc[mf][nf][half * 2]     * scale) : 0.f;
                float e1 = (col + 1 <= qrow) ? __expf(acc[mf][nf][half * 2 + 1] * scale) : 0.f;
                rowpart[mf][half] += e0 + e1;
                __half* dst = g_Ph + ((size_t)b * SEQ + qrow) * SEQ + col;
                *reinterpret_cast<__half2*>(dst) =
                    __halves2half2(__float2half_rn(e0), __float2half_rn(e1));
            }
        }
    }

    // reduce over t lanes (xor 1, 2 stay within same g) then across the 4 wn warps
    extern __shared__ char rawsm[];
    float (*spart)[4] = reinterpret_cast<float (*)[4]>(rawsm);  // [128][4]

#pragma unroll
    for (int mf = 0; mf < 4; ++mf)
#pragma unroll
        for (int half = 0; half < 2; ++half) {
            float r = rowpart[mf][half];
            r += __shfl_xor_sync(0xffffffffu, r, 1);
            r += __shfl_xor_sync(0xffffffffu, r, 2);
            if (t == 0) spart[wm * 64 + mf * 16 + g + half * 8][wn] = r;
        }
    __syncthreads();

    if (threadIdx.x < 128) {
        const int lrow = threadIdx.x;
        float L = (spart[lrow][0] + spart[lrow][1]) + (spart[lrow][2] + spart[lrow][3]);
        g_Lpart[(((size_t)(b * 32 + qt)) * 128 + lrow) * 32 + kt] = L;
    }
}

// PV (normalizes by row sums in epilogue): grid (4 ntile, 32 qt, 4 b)
__global__ __launch_bounds__(NTHR) void pv_kernel(float* __restrict__ out) {
    const int nt = blockIdx.x, qt = blockIdx.y, b = blockIdx.z;

    const size_t poff = ((size_t)b * SEQ + (size_t)qt * 128) * SEQ;
    const __half* Vb = g_Vf + (size_t)b * SEQ * DIM + nt * 128;
    const int kmax = (qt + 1) * 128;

    float acc[4][4][4];
    gemm_fp16_pv(g_Ph + poff, SEQ, Vb, kmax, acc);

    const int lane = threadIdx.x & 31, wid = threadIdx.x >> 5;
    const int wm = wid >> 2, wn = wid & 3;
    const int g = lane >> 2, t = lane & 3;
    const float* Lp = g_Lpart + ((size_t)(b * 32 + qt)) * 128 * 32;

#pragma unroll
    for (int mf = 0; mf < 4; ++mf) {
#pragma unroll
        for (int half = 0; half < 2; ++half) {
            const int lrow = wm * 64 + mf * 16 + g + half * 8;
            float L = 0.f;
            for (int k = 0; k <= qt; ++k) L += Lp[lrow * 32 + k];
            const float inv = 1.0f / L;
            const int row = qt * 128 + lrow;
#pragma unroll
            for (int nf = 0; nf < 4; ++nf) {
                const int col = nt * 128 + wn * 32 + nf * 8 + 2 * t;
                float* dst = out + ((size_t)b * SEQ + row) * DIM + col;
                *reinterpret_cast<float2*>(dst) =
                    make_float2(acc[mf][nf][half * 2] * inv, acc[mf][nf][half * 2 + 1] * inv);
            }
        }
    }
}

// ---------------- launch ----------------
extern "C" void kernel_launch(void* const* d_in, const int* in_sizes, int n_in,
                              void* d_out, int out_size)
{
    const float* x  = (const float*)d_in[0];
    const float* WQ = (const float*)d_in[1];
    const float* WK = (const float*)d_in[2];
    const float* WV = (const float*)d_in[3];
    float* out = (float*)d_out;

    cudaFuncSetAttribute(proj_kernel,   cudaFuncAttributeMaxDynamicSharedMemorySize, SMEM_ALLOC3);
    cudaFuncSetAttribute(scores_kernel, cudaFuncAttributeMaxDynamicSharedMemorySize, SMEM_ALLOC3);
    cudaFuncSetAttribute(pv_kernel,     cudaFuncAttributeMaxDynamicSharedMemorySize, SMEM_ALLOCP);

    convert_kernel<<<2240, 1024>>>(x, WQ, WK, WV);

    proj_kernel<<<dim3(4, 128, 3), NTHR, SMEM_ALLOC3>>>();

    scores_kernel<<<dim3(32, 32, 4), NTHR, SMEM_ALLOC3>>>();

    pv_kernel<<<dim3(4, 32, 4), NTHR, SMEM_ALLOCP>>>(out);
}

// round 14
// speedup vs baseline: 4.3888x; 1.0107x over previous
#include <cuda_runtime.h>
#include <cuda_fp16.h>
#include <cstdint>

#define BATCH 4
#define SEQ   4096
#define DIM   512

#define NSD (4ull*4096ull*512ull)     // 8,388,608
#define NW  (3ull*512ull*512ull)      // 786,432
#define NSS (4ull*4096ull*4096ull)    // 67,108,864

// ---------------- static scratch (allocation-free) ----------------
__device__ __half g_Xf[NSD];                 // X plain fp16
__device__ __half g_Wf[NW];                  // weights plain fp16
__device__ __half g_Qf[NSD];
__device__ __half g_Kf[NSD];
__device__ __half g_Vf[NSD];
__device__ __half g_Ph[NSS];                 // unnormalized exp(scores), fp16
__device__ float  g_Lpart[(size_t)BATCH * 32 * 128 * 32];  // [b][qt][row][kt], 2 MB

// ---------------- PTX helpers (compute_103-baseline ISA only) ----------------
__device__ __forceinline__ uint32_t smem_u32(const void* p) {
    uint32_t a;
    asm("{ .reg .u64 t; cvta.to.shared.u64 t, %1; cvt.u32.u64 %0, t; }" : "=r"(a) : "l"(p));
    return a;
}

__device__ __forceinline__ void cp16(uint32_t s, const void* g) {
    asm volatile("cp.async.cg.shared.global [%0], [%1], 16;" :: "r"(s), "l"(g) : "memory");
}
#define CP_COMMIT() asm volatile("cp.async.commit_group;" ::: "memory")
#define CP_WAIT(n)  asm volatile("cp.async.wait_group %0;" :: "n"(n) : "memory")

__device__ __forceinline__ void ldm4(uint32_t addr, uint32_t r[4]) {
    asm volatile("ldmatrix.sync.aligned.m8n8.x4.shared.b16 {%0,%1,%2,%3}, [%4];"
                 : "=r"(r[0]), "=r"(r[1]), "=r"(r[2]), "=r"(r[3]) : "r"(addr));
}

__device__ __forceinline__ void ldm4t(uint32_t addr, uint32_t r[4]) {
    asm volatile("ldmatrix.sync.aligned.m8n8.x4.trans.shared.b16 {%0,%1,%2,%3}, [%4];"
                 : "=r"(r[0]), "=r"(r[1]), "=r"(r[2]), "=r"(r[3]) : "r"(addr));
}

__device__ __forceinline__ void mma_hf(float* c, const uint32_t* a, uint32_t b0, uint32_t b1) {
    asm volatile(
        "mma.sync.aligned.m16n8k16.row.col.f32.f16.f16.f32 "
        "{%0,%1,%2,%3}, {%4,%5,%6,%7}, {%8,%9}, {%0,%1,%2,%3};"
        : "+f"(c[0]), "+f"(c[1]), "+f"(c[2]), "+f"(c[3])
        : "r"(a[0]), "r"(a[1]), "r"(a[2]), "r"(a[3]), "r"(b0), "r"(b1));
}

// ---------------- GEMM config ----------------
#define ROWP     144
#define TILE_B   (128 * ROWP)          // 18432
#define ROWB     272
#define TILE_BB  (64 * ROWB)           // 17408
#define OFF3_A   0
#define OFF3_B   (1 * TILE_B)
#define STAGE3_B (2 * TILE_B)          // 36864
#define SMEM_ALLOC3 (2 * STAGE3_B)     // 73728
#define OFFP_A   0
#define OFFP_B   TILE_B
#define STAGEP_B (TILE_B + TILE_BB)    // 35840
#define SMEM_ALLOCP (2 * STAGEP_B)     // 71680
#define NTHR     256

template <typename T>
__device__ __forceinline__ void fill_tile(uint32_t sb, const T* __restrict__ src,
                                          int ld, int k0, int tid) {
#pragma unroll
    for (int v = 0; v < 4; ++v) {
        int idx = v * NTHR + tid;
        int row = idx >> 3;
        int c16 = idx & 7;
        cp16(sb + row * ROWP + c16 * 16, src + (size_t)row * ld + k0 + c16 * 8);
    }
}

__device__ __forceinline__ void fill_vtile(uint32_t sb, const __half* __restrict__ src,
                                           int k0, int tid) {
#pragma unroll
    for (int v = 0; v < 4; ++v) {
        int idx = v * NTHR + tid;
        int row = idx >> 4;
        int c16 = idx & 15;
        cp16(sb + row * ROWB + c16 * 16, src + (size_t)(k0 + row) * DIM + c16 * 8);
    }
}

// ---------------- plain fp16 mainloop (proj & scores) ----------------
__device__ __forceinline__ void gemm_fp16(
    const __half* __restrict__ A, int lda,
    const __half* __restrict__ B, int ldb,
    int ktotal, float acc[4][4][4])
{
    extern __shared__ char rawsm[];
    const uint32_t smb = smem_u32(rawsm);
    const int tid  = threadIdx.x;
    const int lane = tid & 31;
    const int wid  = tid >> 5;
    const int wm   = wid >> 2;
    const int wn   = wid & 3;

#pragma unroll
    for (int i = 0; i < 4; ++i)
#pragma unroll
        for (int j = 0; j < 4; ++j)
#pragma unroll
            for (int k = 0; k < 4; ++k) acc[i][j][k] = 0.f;

    const int nch = ktotal >> 6;

    fill_tile(smb + OFF3_A, A, lda, 0, tid);
    fill_tile(smb + OFF3_B, B, ldb, 0, tid);
    CP_COMMIT();

    const uint32_t a_row_off = (uint32_t)((wm * 64 + (lane & 15)) * ROWP);
    const uint32_t b_row_off = (uint32_t)((wn * 32 + (lane & 7) + ((lane >> 3) & 1) * 8) * ROWP);
    const uint32_t k_half    = (uint32_t)(((lane >> 4) & 1) * 16);

    for (int c = 0; c < nch; ++c) {
        CP_WAIT(0);
        __syncthreads();
        if (c + 1 < nch) {
            const uint32_t nb = smb + (uint32_t)(((c + 1) & 1) * STAGE3_B);
            const int nk = (c + 1) << 6;
            fill_tile(nb + OFF3_A, A, lda, nk, tid);
            fill_tile(nb + OFF3_B, B, ldb, nk, tid);
            CP_COMMIT();
        }

        const uint32_t sb = smb + (uint32_t)((c & 1) * STAGE3_B);

#pragma unroll
        for (int ks = 0; ks < 4; ++ks) {
            const uint32_t ko = (uint32_t)(ks * 32) + k_half;

            uint32_t ra[4][4], rb[2][4];
#pragma unroll
            for (int mf = 0; mf < 4; ++mf)
                ldm4(sb + OFF3_A + a_row_off + (uint32_t)(mf * 16 * ROWP) + ko, ra[mf]);
#pragma unroll
            for (int bf = 0; bf < 2; ++bf)
                ldm4(sb + OFF3_B + b_row_off + (uint32_t)(bf * 16 * ROWP) + ko, rb[bf]);

#pragma unroll
            for (int mf = 0; mf < 4; ++mf)
#pragma unroll
                for (int bf = 0; bf < 2; ++bf) {
                    mma_hf(acc[mf][bf * 2],     ra[mf], rb[bf][0], rb[bf][2]);
                    mma_hf(acc[mf][bf * 2 + 1], ra[mf], rb[bf][1], rb[bf][3]);
                }
        }
    }
    __syncthreads();
}

// ---------------- pv mainloop: B from natural V via ldmatrix.trans ----------
__device__ __forceinline__ void gemm_fp16_pv(
    const __half* __restrict__ A, int lda,
    const __half* __restrict__ V,
    int ktotal, float acc[4][4][4])
{
    extern __shared__ char rawsm[];
    const uint32_t smb = smem_u32(rawsm);
    const int tid  = threadIdx.x;
    const int lane = tid & 31;
    const int wid  = tid >> 5;
    const int wm   = wid >> 2;
    const int wn   = wid & 3;

#pragma unroll
    for (int i = 0; i < 4; ++i)
#pragma unroll
        for (int j = 0; j < 4; ++j)
#pragma unroll
            for (int k = 0; k < 4; ++k) acc[i][j][k] = 0.f;

    const int nch = ktotal >> 6;

    fill_tile(smb + OFFP_A, A, lda, 0, tid);
    fill_vtile(smb + OFFP_B, V, 0, tid);
    CP_COMMIT();

    const uint32_t a_row_off = (uint32_t)((wm * 64 + (lane & 15)) * ROWP);
    const uint32_t k_half    = (uint32_t)(((lane >> 4) & 1) * 16);
    const uint32_t bt_off = (uint32_t)(((lane & 7) + ((lane >> 4) & 1) * 8) * ROWB
                                       + wn * 64 + ((lane >> 3) & 1) * 16);

    for (int c = 0; c < nch; ++c) {
        CP_WAIT(0);
        __syncthreads();
        if (c + 1 < nch) {
            const uint32_t nb = smb + (uint32_t)(((c + 1) & 1) * STAGEP_B);
            const int nk = (c + 1) << 6;
            fill_tile(nb + OFFP_A, A, lda, nk, tid);
            fill_vtile(nb + OFFP_B, V, nk, tid);
            CP_COMMIT();
        }

        const uint32_t sb = smb + (uint32_t)((c & 1) * STAGEP_B);

#pragma unroll
        for (int ks = 0; ks < 4; ++ks) {
            const uint32_t ko = (uint32_t)(ks * 32) + k_half;

            uint32_t ra[4][4], rb[2][4];
#pragma unroll
            for (int mf = 0; mf < 4; ++mf)
                ldm4(sb + OFFP_A + a_row_off + (uint32_t)(mf * 16 * ROWP) + ko, ra[mf]);
#pragma unroll
            for (int bf = 0; bf < 2; ++bf)
                ldm4t(sb + OFFP_B + (uint32_t)(ks * 16 * ROWB) + bt_off + (uint32_t)(bf * 32),
                      rb[bf]);

#pragma unroll
            for (int mf = 0; mf < 4; ++mf)
#pragma unroll
                for (int bf = 0; bf < 2; ++bf) {
                    mma_hf(acc[mf][bf * 2],     ra[mf], rb[bf][0], rb[bf][2]);
                    mma_hf(acc[mf][bf * 2 + 1], ra[mf], rb[bf][1], rb[bf][3]);
                }
        }
    }
    __syncthreads();
}

// ---------------- stage kernels ----------------

// X and W -> plain fp16, vectorized 4-wide, one launch
__global__ __launch_bounds__(1024) void convert_kernel(const float* __restrict__ x,
                                                       const float* __restrict__ wq,
                                                       const float* __restrict__ wk,
                                                       const float* __restrict__ wv) {
    size_t i = (size_t)blockIdx.x * blockDim.x + threadIdx.x;   // float4 index
    const size_t nx4 = NSD >> 2, nw4 = NW >> 2, nwq4 = (NW / 3) >> 2;
    if (i < nx4) {
        float4 v = reinterpret_cast<const float4*>(x)[i];
        __half2 h0 = __halves2half2(__float2half_rn(v.x), __float2half_rn(v.y));
        __half2 h1 = __halves2half2(__float2half_rn(v.z), __float2half_rn(v.w));
        reinterpret_cast<__half2*>(g_Xf)[i * 2]     = h0;
        reinterpret_cast<__half2*>(g_Xf)[i * 2 + 1] = h1;
    } else if (i < nx4 + nw4) {
        size_t j = i - nx4;
        size_t which = j / nwq4;
        size_t off   = j - which * nwq4;
        const float* src = (which == 0) ? wq : (which == 1) ? wk : wv;
        float4 v = reinterpret_cast<const float4*>(src)[off];
        __half2 h0 = __halves2half2(__float2half_rn(v.x), __float2half_rn(v.y));
        __half2 h1 = __halves2half2(__float2half_rn(v.z), __float2half_rn(v.w));
        reinterpret_cast<__half2*>(g_Wf)[j * 2]     = h0;
        reinterpret_cast<__half2*>(g_Wf)[j * 2 + 1] = h1;
    }
}

// QKV projection: grid (4 ntile, 128 mtile, 3 which)
__global__ __launch_bounds__(NTHR) void proj_kernel() {
    const int nt = blockIdx.x, mt = blockIdx.y, z = blockIdx.z;
    const __half* A = g_Xf + (size_t)mt * 128 * DIM;
    const __half* B = g_Wf + (size_t)z * DIM * DIM + (size_t)nt * 128 * DIM;

    float acc[4][4][4];
    gemm_fp16(A, DIM, B, DIM, DIM, acc);

    __half* dst0 = (z == 0) ? g_Qf : (z == 1) ? g_Kf : g_Vf;

    const int lane = threadIdx.x & 31, wid = threadIdx.x >> 5;
    const int wm = wid >> 2, wn = wid & 3;
    const int g = lane >> 2, t = lane & 3;
    const size_t rbase = (size_t)mt * 128;
    const int cbase = nt * 128 + wn * 32 + 2 * t;

#pragma unroll
    for (int mf = 0; mf < 4; ++mf) {
#pragma unroll
        for (int nf = 0; nf < 4; ++nf) {
            const int col = cbase + nf * 8;
#pragma unroll
            for (int half = 0; half < 2; ++half) {
                const int row = wm * 64 + mf * 16 + g + half * 8;
                float v0 = acc[mf][nf][half * 2];
                float v1 = acc[mf][nf][half * 2 + 1];
                size_t o = (rbase + row) * DIM + col;
                *reinterpret_cast<__half2*>(dst0 + o) =
                    __halves2half2(__float2half_rn(v0), __float2half_rn(v1));
            }
        }
    }
}

// Scores + exp + per-tile row sums. Compact triangular grid: (528 pairs, 4 b).
__global__ __launch_bounds__(NTHR) void scores_kernel() {
    // decode linear pair index -> (qt, kt), kt <= qt
    const int l = blockIdx.x;
    int qt = (int)((sqrtf(8.f * (float)l + 1.f) - 1.f) * 0.5f);
    while ((qt + 1) * (qt + 2) / 2 <= l) ++qt;
    while (qt * (qt + 1) / 2 > l) --qt;
    const int kt = l - qt * (qt + 1) / 2;
    const int b = blockIdx.y;

    const size_t qoff = ((size_t)b * SEQ + (size_t)qt * 128) * DIM;
    const size_t koff = ((size_t)b * SEQ + (size_t)kt * 128) * DIM;

    float acc[4][4][4];
    gemm_fp16(g_Qf + qoff, DIM, g_Kf + koff, DIM, DIM, acc);

    const int lane = threadIdx.x & 31, wid = threadIdx.x >> 5;
    const int wm = wid >> 2, wn = wid & 3;
    const int g = lane >> 2, t = lane & 3;
    const float scale = 0.04419417382415922f;   // 1/sqrt(512)

    float rowpart[4][2];
#pragma unroll
    for (int mf = 0; mf < 4; ++mf) { rowpart[mf][0] = 0.f; rowpart[mf][1] = 0.f; }

#pragma unroll
    for (int mf = 0; mf < 4; ++mf) {
#pragma unroll
        for (int nf = 0; nf < 4; ++nf) {
            const int col = kt * 128 + wn * 32 + nf * 8 + 2 * t;
#pragma unroll
            for (int half = 0; half < 2; ++half) {
                const int lrow = wm * 64 + mf * 16 + g + half * 8;
                const int qrow = qt * 128 + lrow;
                float e0 = (col     <= qrow) ? __expf(acc[mf][nf][half * 2]     * scale) : 0.f;
                float e1 = (col + 1 <= qrow) ? __expf(acc[mf][nf][half * 2 + 1] * scale) : 0.f;
                rowpart[mf][half] += e0 + e1;
                __half* dst = g_Ph + ((size_t)b * SEQ + qrow) * SEQ + col;
                *reinterpret_cast<__half2*>(dst) =
                    __halves2half2(__float2half_rn(e0), __float2half_rn(e1));
            }
        }
    }

    extern __shared__ char rawsm[];
    float (*spart)[4] = reinterpret_cast<float (*)[4]>(rawsm);  // [128][4]

#pragma unroll
    for (int mf = 0; mf < 4; ++mf)
#pragma unroll
        for (int half = 0; half < 2; ++half) {
            float r = rowpart[mf][half];
            r += __shfl_xor_sync(0xffffffffu, r, 1);
            r += __shfl_xor_sync(0xffffffffu, r, 2);
            if (t == 0) spart[wm * 64 + mf * 16 + g + half * 8][wn] = r;
        }
    __syncthreads();

    if (threadIdx.x < 128) {
        const int lrow = threadIdx.x;
        float L = (spart[lrow][0] + spart[lrow][1]) + (spart[lrow][2] + spart[lrow][3]);
        g_Lpart[(((size_t)(b * 32 + qt)) * 128 + lrow) * 32 + kt] = L;
    }
}

// PV (normalizes by row sums in epilogue): grid (4 ntile, 32 qt, 4 b).
// qt REVERSED so the heaviest CTAs (largest causal extent) launch first.
__global__ __launch_bounds__(NTHR) void pv_kernel(float* __restrict__ out) {
    const int nt = blockIdx.x, qt = 31 - blockIdx.y, b = blockIdx.z;

    const size_t poff = ((size_t)b * SEQ + (size_t)qt * 128) * SEQ;
    const __half* Vb = g_Vf + (size_t)b * SEQ * DIM + nt * 128;
    const int kmax = (qt + 1) * 128;

    float acc[4][4][4];
    gemm_fp16_pv(g_Ph + poff, SEQ, Vb, kmax, acc);

    const int lane = threadIdx.x & 31, wid = threadIdx.x >> 5;
    const int wm = wid >> 2, wn = wid & 3;
    const int g = lane >> 2, t = lane & 3;
    const float* Lp = g_Lpart + ((size_t)(b * 32 + qt)) * 128 * 32;

#pragma unroll
    for (int mf = 0; mf < 4; ++mf) {
#pragma unroll
        for (int half = 0; half < 2; ++half) {
            const int lrow = wm * 64 + mf * 16 + g + half * 8;
            float L = 0.f;
            for (int k = 0; k <= qt; ++k) L += Lp[lrow * 32 + k];
            const float inv = 1.0f / L;
            const int row = qt * 128 + lrow;
#pragma unroll
            for (int nf = 0; nf < 4; ++nf) {
                const int col = nt * 128 + wn * 32 + nf * 8 + 2 * t;
                float* dst = out + ((size_t)b * SEQ + row) * DIM + col;
                *reinterpret_cast<float2*>(dst) =
                    make_float2(acc[mf][nf][half * 2] * inv, acc[mf][nf][half * 2 + 1] * inv);
            }
        }
    }
}

// ---------------- launch ----------------
extern "C" void kernel_launch(void* const* d_in, const int* in_sizes, int n_in,
                              void* d_out, int out_size)
{
    const float* x  = (const float*)d_in[0];
    const float* WQ = (const float*)d_in[1];
    const float* WK = (const float*)d_in[2];
    const float* WV = (const float*)d_in[3];
    float* out = (float*)d_out;

    cudaFuncSetAttribute(proj_kernel,   cudaFuncAttributeMaxDynamicSharedMemorySize, SMEM_ALLOC3);
    cudaFuncSetAttribute(scores_kernel, cudaFuncAttributeMaxDynamicSharedMemorySize, SMEM_ALLOC3);
    cudaFuncSetAttribute(pv_kernel,     cudaFuncAttributeMaxDynamicSharedMemorySize, SMEM_ALLOCP);

    convert_kernel<<<2240, 1024>>>(x, WQ, WK, WV);

    proj_kernel<<<dim3(4, 128, 3), NTHR, SMEM_ALLOC3>>>();

    scores_kernel<<<dim3(528, 4), NTHR, SMEM_ALLOC3>>>();

    pv_kernel<<<dim3(4, 32, 4), NTHR, SMEM_ALLOCP>>>(out);
}